// round 1
// baseline (speedup 1.0000x reference)
#include <cuda_runtime.h>
#include <math_constants.h>

// Problem constants
#define B_   16
#define T_   128
#define N_   50
#define D_   512
#define H_   8
#define DH   64
#define TOK  (B_ * T_ * N_)      // 102400 tokens
#define K3   (3 * D_)            // 1536

// Scratch (device globals: allocation-free per harness rules)
__device__ float g_H[(size_t)TOK * K3];     // packed [X, TLE]  (629 MB)
__device__ float g_q[(size_t)TOK * D_];
__device__ float g_k[(size_t)TOK * D_];
__device__ float g_v[(size_t)TOK * D_];
__device__ float g_attn[(size_t)TOK * D_];
__device__ float g_mid[(size_t)TOK * D_];

// ---------------------------------------------------------------------------
// Pack H = concat(X, TLE) along last dim. float4 granularity (512/1024 both
// divisible by 4 so a float4 never straddles the concat boundary).
// ---------------------------------------------------------------------------
__global__ void build_H_kernel(const float* __restrict__ X,
                               const float* __restrict__ TLE) {
    size_t i = ((size_t)blockIdx.x * blockDim.x + threadIdx.x) * 4;
    size_t tok = i / K3;
    int c = (int)(i % K3);
    float4 val;
    if (c < D_) val = *(const float4*)(X + tok * D_ + c);
    else        val = *(const float4*)(TLE + tok * (size_t)(2 * D_) + (c - D_));
    *(float4*)(g_H + i) = val;
}

// ---------------------------------------------------------------------------
// Tiled SGEMM: C[M,512] = act(A[M,K] @ W[K,512] + bias)
// BM=BN=128, BK=8, 256 threads, 8x8 per thread. M=102400, N=512, K in {512,1536}
// — all dims divide the tiles, so no bounds checks.
// ---------------------------------------------------------------------------
template<int ACT>
__global__ void __launch_bounds__(256)
gemm128_kernel(const float* __restrict__ A, const float* __restrict__ W,
               const float* __restrict__ bias, float* __restrict__ C, int K) {
    const int N = 512;
    __shared__ float As[8][128];
    __shared__ float Bs[8][128];

    int tid  = threadIdx.x;
    int aRow = tid >> 1;            // 0..127
    int aCol = (tid & 1) << 2;      // 0 or 4
    int bRow = tid >> 5;            // 0..7
    int bCol = (tid & 31) << 2;     // 0..124
    int cRow = (tid >> 4) << 3;     // 0..120
    int cCol = (tid & 15) << 3;     // 0..120

    const float* Ab = A + (size_t)blockIdx.y * 128 * K;
    const float* Wb = W + blockIdx.x * 128;

    float acc[8][8];
#pragma unroll
    for (int i = 0; i < 8; i++)
#pragma unroll
        for (int j = 0; j < 8; j++) acc[i][j] = 0.f;

    for (int k0 = 0; k0 < K; k0 += 8) {
        float4 a4 = *(const float4*)(Ab + (size_t)aRow * K + k0 + aCol);
        As[aCol + 0][aRow] = a4.x;
        As[aCol + 1][aRow] = a4.y;
        As[aCol + 2][aRow] = a4.z;
        As[aCol + 3][aRow] = a4.w;
        *(float4*)&Bs[bRow][bCol] =
            *(const float4*)(Wb + (size_t)(k0 + bRow) * N + bCol);
        __syncthreads();
#pragma unroll
        for (int kk = 0; kk < 8; kk++) {
            float ar[8], br[8];
#pragma unroll
            for (int i = 0; i < 8; i += 4)
                *(float4*)&ar[i] = *(float4*)&As[kk][cRow + i];
#pragma unroll
            for (int j = 0; j < 8; j += 4)
                *(float4*)&br[j] = *(float4*)&Bs[kk][cCol + j];
#pragma unroll
            for (int i = 0; i < 8; i++)
#pragma unroll
                for (int j = 0; j < 8; j++)
                    acc[i][j] += ar[i] * br[j];
        }
        __syncthreads();
    }

    int row0 = blockIdx.y * 128 + cRow;
    int col0 = blockIdx.x * 128 + cCol;
    float bj[8];
#pragma unroll
    for (int j = 0; j < 8; j += 4)
        *(float4*)&bj[j] = *(const float4*)(bias + col0 + j);
#pragma unroll
    for (int i = 0; i < 8; i++) {
#pragma unroll
        for (int j = 0; j < 8; j++) {
            float x = acc[i][j] + bj[j];
            if (ACT) x = fmaxf(x, 0.f);
            acc[i][j] = x;
        }
#pragma unroll
        for (int j = 0; j < 8; j += 4)
            *(float4*)(C + (size_t)(row0 + i) * N + col0 + j) = *(float4*)&acc[i][j];
    }
}

// ---------------------------------------------------------------------------
// Fused causal attention with online softmax.
// One block per (b, n, head): 128 threads, each thread owns one query row.
// K/V staged through smem in two 64-row chunks (32 KB static smem).
// ---------------------------------------------------------------------------
__global__ void __launch_bounds__(128)
attn_kernel(const int* __restrict__ kpm) {
    __shared__ float ks[64][64];
    __shared__ float vs[64][64];

    int bid = blockIdx.x;              // ((b*N_)+n)*H_ + h
    int h = bid & 7;
    int n = (bid >> 3) % N_;
    int b = bid / (H_ * N_);
    int tq = threadIdx.x;              // query row
    int L  = kpm[b];                   // valid key length in [1, T]

    size_t base = ((size_t)(b * T_) * N_ + n) * D_ + h * DH;   // token (b,0,n), this head
    const size_t rstride = (size_t)N_ * D_;                    // stride per time step

    float qr[DH], acc[DH];
    const float* qp = g_q + base + (size_t)tq * rstride;
#pragma unroll
    for (int d = 0; d < DH; d += 4) {
        float4 t4 = *(const float4*)(qp + d);
        qr[d] = t4.x; qr[d + 1] = t4.y; qr[d + 2] = t4.z; qr[d + 3] = t4.w;
    }
#pragma unroll
    for (int d = 0; d < DH; d++) acc[d] = 0.f;

    float m = -CUDART_INF_F, l = 0.f;
    int pmax = min(tq, L - 1);         // always >= 0

    for (int c0 = 0; c0 < T_; c0 += 64) {
        __syncthreads();
        // cooperative load of 64 K rows and 64 V rows (float4 each)
#pragma unroll
        for (int e = threadIdx.x * 4; e < 64 * 64; e += 128 * 4) {
            int r = e >> 6, d = e & 63;
            size_t off = base + (size_t)(c0 + r) * rstride + d;
            *(float4*)&ks[r][d] = *(const float4*)(g_k + off);
            *(float4*)&vs[r][d] = *(const float4*)(g_v + off);
        }
        __syncthreads();

        int pend = min(pmax, c0 + 63);
        for (int p = c0; p <= pend; p++) {
            const float* kr = ks[p - c0];
            float s = 0.f;
#pragma unroll
            for (int d = 0; d < DH; d++) s += qr[d] * kr[d];
            s *= 0.125f;                          // 1/sqrt(64)

            float mn   = fmaxf(m, s);
            float corr = __expf(m - mn);          // first iter: exp(-inf)=0
            float e1   = __expf(s - mn);
            l = l * corr + e1;
            const float* vr = vs[p - c0];
#pragma unroll
            for (int d = 0; d < DH; d++)
                acc[d] = acc[d] * corr + e1 * vr[d];
            m = mn;
        }
    }

    float inv = 1.f / l;
    float* op = g_attn + base + (size_t)tq * rstride;
#pragma unroll
    for (int d = 0; d < DH; d += 4) {
        float4 o;
        o.x = acc[d] * inv; o.y = acc[d + 1] * inv;
        o.z = acc[d + 2] * inv; o.w = acc[d + 3] * inv;
        *(float4*)(op + d) = o;
    }
}

// ---------------------------------------------------------------------------
extern "C" void kernel_launch(void* const* d_in, const int* in_sizes, int n_in,
                              void* d_out, int out_size) {
    const float* X   = (const float*)d_in[0];
    const float* TLE = (const float*)d_in[1];
    const int*   kpm = (const int*)  d_in[2];
    const float* Wq  = (const float*)d_in[3];
    const float* bq  = (const float*)d_in[4];
    const float* Wk  = (const float*)d_in[5];
    const float* bk  = (const float*)d_in[6];
    const float* Wv  = (const float*)d_in[7];
    const float* bv  = (const float*)d_in[8];
    const float* W1  = (const float*)d_in[9];
    const float* b1  = (const float*)d_in[10];
    const float* W2  = (const float*)d_in[11];
    const float* b2  = (const float*)d_in[12];
    float* out = (float*)d_out;

    float *pH, *pq, *pk, *pv, *pa, *pm;
    cudaGetSymbolAddress((void**)&pH, g_H);
    cudaGetSymbolAddress((void**)&pq, g_q);
    cudaGetSymbolAddress((void**)&pk, g_k);
    cudaGetSymbolAddress((void**)&pv, g_v);
    cudaGetSymbolAddress((void**)&pa, g_attn);
    cudaGetSymbolAddress((void**)&pm, g_mid);

    // 1. pack H
    build_H_kernel<<<(size_t)TOK * K3 / 4 / 256, 256>>>(X, TLE);

    // 2. QKV projections (relu epilogue)
    dim3 gq(512 / 128, TOK / 128);   // (4, 800)
    gemm128_kernel<1><<<gq, 256>>>(pH, Wq, bq, pq, K3);
    gemm128_kernel<1><<<gq, 256>>>(pH, Wk, bk, pk, K3);
    gemm128_kernel<1><<<gq, 256>>>(pH, Wv, bv, pv, K3);

    // 3. fused causal attention
    attn_kernel<<<B_ * N_ * H_, 128>>>(kpm);

    // 4. FFN
    gemm128_kernel<1><<<gq, 256>>>(pa, W1, b1, pm, D_);
    gemm128_kernel<0><<<gq, 256>>>(pm, W2, b2, out, D_);
}

// round 3
// speedup vs baseline: 2.5506x; 2.5506x over previous
#include <cuda_runtime.h>
#include <cuda_bf16.h>
#include <math_constants.h>
#include <cstdint>

// Problem constants
#define B_   16
#define T_   128
#define N_   50
#define D_   512
#define H_   8
#define DH   64
#define TOK  (B_ * T_ * N_)      // 102400 tokens
#define K3   (3 * D_)            // 1536

// ---------------------------------------------------------------------------
// Scratch (device globals: allocation-free per harness rules)
// ---------------------------------------------------------------------------
__device__ __nv_bfloat16 g_Ahi[(size_t)TOK * K3];   // split activations (hi)
__device__ __nv_bfloat16 g_Alo[(size_t)TOK * K3];   // split activations (lo)
__device__ float g_q[(size_t)TOK * D_];
__device__ float g_k[(size_t)TOK * D_];
__device__ float g_v[(size_t)TOK * D_];
__device__ float g_attn[(size_t)TOK * D_];
__device__ float g_mid[(size_t)TOK * D_];
// transposed bf16 weights: Wq,Wk,Wv (512x1536 each), W1,W2 (512x512 each)
#define WOFF_Q 0
#define WOFF_K 786432
#define WOFF_V 1572864
#define WOFF_1 2359296
#define WOFF_2 2621440
__device__ __nv_bfloat16 g_Wthi[2883584];
__device__ __nv_bfloat16 g_Wtlo[2883584];

// ---------------------------------------------------------------------------
// helpers
// ---------------------------------------------------------------------------
__device__ __forceinline__ uint32_t smem_u32(const void* p) {
    uint32_t a;
    asm("{ .reg .u64 t; cvta.to.shared.u64 t, %1; cvt.u32.u64 %0, t; }"
        : "=r"(a) : "l"(p));
    return a;
}

#define LDSM_X4(r0, r1, r2, r3, addr)                                         \
    asm volatile("ldmatrix.sync.aligned.m8n8.x4.shared.b16 {%0,%1,%2,%3}, [%4];" \
                 : "=r"(r0), "=r"(r1), "=r"(r2), "=r"(r3) : "r"(addr))

#define MMA16816(d, a, b)                                                     \
    asm volatile("mma.sync.aligned.m16n8k16.row.col.f32.bf16.bf16.f32 "       \
                 "{%0,%1,%2,%3}, {%4,%5,%6,%7}, {%8,%9}, {%0,%1,%2,%3};"      \
                 : "+f"((d)[0]), "+f"((d)[1]), "+f"((d)[2]), "+f"((d)[3])     \
                 : "r"((a)[0]), "r"((a)[1]), "r"((a)[2]), "r"((a)[3]),        \
                   "r"((b)[0]), "r"((b)[1]))

// ---------------------------------------------------------------------------
// fp32 -> (bf16 hi, bf16 lo) split, 8 elems / thread
// ---------------------------------------------------------------------------
__device__ __forceinline__ void split8(__nv_bfloat16* hi, __nv_bfloat16* lo,
                                       float4 a, float4 b) {
    float f[8] = {a.x, a.y, a.z, a.w, b.x, b.y, b.z, b.w};
    __nv_bfloat16 h[8], l[8];
#pragma unroll
    for (int j = 0; j < 8; j++) {
        h[j] = __float2bfloat16(f[j]);
        l[j] = __float2bfloat16(f[j] - __bfloat162float(h[j]));
    }
    *(uint4*)hi = *(uint4*)h;
    *(uint4*)lo = *(uint4*)l;
}

// H = concat(X, TLE), split into hi/lo bf16 directly
__global__ void conv_H_kernel(const float* __restrict__ X,
                              const float* __restrict__ TLE) {
    size_t i = ((size_t)blockIdx.x * 256 + threadIdx.x) * 8;
    size_t tok = i / K3;
    int c = (int)(i % K3);
    const float* src = (c < D_) ? (X + tok * D_ + c)
                                : (TLE + tok * (size_t)(2 * D_) + (c - D_));
    float4 a = *(const float4*)src;
    float4 b = *(const float4*)(src + 4);
    split8(g_Ahi + i, g_Alo + i, a, b);
}

// generic fp32 array -> hi/lo split (for attn output and FFN mid)
__global__ void conv_split_kernel(const float* __restrict__ s) {
    size_t i = ((size_t)blockIdx.x * 256 + threadIdx.x) * 8;
    float4 a = *(const float4*)(s + i);
    float4 b = *(const float4*)(s + i + 4);
    split8(g_Ahi + i, g_Alo + i, a, b);
}

// W [K,512] fp32 -> Wt [512,K] bf16 hi/lo
__global__ void wtrans_kernel(const float* __restrict__ W,
                              __nv_bfloat16* __restrict__ hi,
                              __nv_bfloat16* __restrict__ lo, int K) {
    int idx = blockIdx.x * 256 + threadIdx.x;
    if (idx >= 512 * K) return;
    int n = idx / K, k = idx - n * K;
    float v = W[(size_t)k * 512 + n];
    __nv_bfloat16 h = __float2bfloat16(v);
    hi[idx] = h;
    lo[idx] = __float2bfloat16(v - __bfloat162float(h));
}

// ---------------------------------------------------------------------------
// Tensor-core GEMM via mma.sync (HMMA): C[M,512] = act(A @ Wt^T + bias)
//   A split bf16 (hi/lo) row-major [M,K]; Wt split bf16 [512,K] K-major
//   (== B col-major). CTA tile 128x128, BK=32, 8 warps (2x4), warp tile
//   64x32. 2-stage cp.async pipeline. 3 MMAs (hh,hl,lh) per tile per kstep.
// ---------------------------------------------------------------------------
#define BK        32
#define PSTRIDE   40                       // bf16 per padded row (80 B)
#define ARR_BYTES (128 * PSTRIDE * 2)      // 10240
#define STAGE_BYTES (4 * ARR_BYTES)        // 40960
#define SMEM_BYTES  (2 * STAGE_BYTES)      // 81920

template<int ACT>
__global__ void __launch_bounds__(256)
mma_gemm_kernel(const __nv_bfloat16* __restrict__ Ahi,
                const __nv_bfloat16* __restrict__ Alo,
                const __nv_bfloat16* __restrict__ Bhi,
                const __nv_bfloat16* __restrict__ Blo,
                const float* __restrict__ bias, float* __restrict__ C, int K) {
    extern __shared__ char sm[];
    uint32_t sbase = smem_u32(sm);

    int tid = threadIdx.x, wid = tid >> 5, lane = tid & 31;
    int warpM = (wid >> 2) * 64;           // 0 or 64
    int warpN = (wid & 3) * 32;            // 0,32,64,96

    const __nv_bfloat16* srcs[4] = {
        Ahi + (size_t)blockIdx.y * 128 * K,
        Alo + (size_t)blockIdx.y * 128 * K,
        Bhi + (size_t)blockIdx.x * 128 * K,
        Blo + (size_t)blockIdx.x * 128 * K
    };

    float acc[4][4][4];
#pragma unroll
    for (int i = 0; i < 4; i++)
#pragma unroll
        for (int j = 0; j < 4; j++)
#pragma unroll
            for (int e = 0; e < 4; e++) acc[i][j][e] = 0.f;

    // per-thread copy decode (8 x 16B segments per stage)
    int cidx[8], carr[8];
    uint32_t csm[8];
#pragma unroll
    for (int j = 0; j < 8; j++) {
        int idx = tid + j * 256;
        int arr = idx >> 9, rem = idx & 511;
        int r = rem >> 2, seg = rem & 3;
        carr[j] = arr;
        cidx[j] = r * K + seg * 8;                       // gmem elem offset (+k0)
        csm[j]  = (uint32_t)(arr * ARR_BYTES + r * (PSTRIDE * 2) + seg * 16);
    }

    auto issue = [&](int c) {
        uint32_t st = sbase + (uint32_t)((c & 1) * STAGE_BYTES);
        int k0 = c * BK;
#pragma unroll
        for (int j = 0; j < 8; j++) {
            const __nv_bfloat16* g = srcs[carr[j]] + cidx[j] + k0;
            asm volatile("cp.async.cg.shared.global [%0], [%1], 16;"
                         :: "r"(st + csm[j]), "l"(g));
        }
        asm volatile("cp.async.commit_group;");
    };

    // ldmatrix per-lane smem offsets (within a stage)
    //   A: m = warpM + mt*16 + (lane%16), k = kk*16 + (lane/16)*8
    uint32_t aoff = (uint32_t)((warpM + (lane & 15)) * (PSTRIDE * 2) + (lane >> 4) * 16);
    //   B: n = warpN + np*16 + ((lane>>4)<<3) + (lane&7), k = kk*16 + ((lane>>3)&1)*8
    uint32_t boff = (uint32_t)(2 * ARR_BYTES +
                    (warpN + ((lane >> 4) << 3) + (lane & 7)) * (PSTRIDE * 2) +
                    ((lane >> 3) & 1) * 16);

    int nch = K / BK;
    issue(0);
    for (int c = 0; c < nch; c++) {
        if (c + 1 < nch) {
            issue(c + 1);
            asm volatile("cp.async.wait_group 1;");
        } else {
            asm volatile("cp.async.wait_group 0;");
        }
        __syncthreads();

        uint32_t stage = sbase + (uint32_t)((c & 1) * STAGE_BYTES);
#pragma unroll
        for (int kk = 0; kk < 2; kk++) {
            uint32_t ah[4][4], al[4][4];
#pragma unroll
            for (int mt = 0; mt < 4; mt++) {
                uint32_t ad = stage + aoff + mt * (16 * PSTRIDE * 2) + kk * 32;
                LDSM_X4(ah[mt][0], ah[mt][1], ah[mt][2], ah[mt][3], ad);
                LDSM_X4(al[mt][0], al[mt][1], al[mt][2], al[mt][3], ad + ARR_BYTES);
            }
            uint32_t bh[4][2], bl[4][2];
#pragma unroll
            for (int np = 0; np < 2; np++) {
                uint32_t bd = stage + boff + np * (16 * PSTRIDE * 2) + kk * 32;
                LDSM_X4(bh[2*np][0], bh[2*np][1], bh[2*np+1][0], bh[2*np+1][1], bd);
                LDSM_X4(bl[2*np][0], bl[2*np][1], bl[2*np+1][0], bl[2*np+1][1],
                        bd + ARR_BYTES);
            }
#pragma unroll
            for (int mt = 0; mt < 4; mt++)
#pragma unroll
                for (int nt = 0; nt < 4; nt++) {
                    MMA16816(acc[mt][nt], ah[mt], bh[nt]);
                    MMA16816(acc[mt][nt], ah[mt], bl[nt]);
                    MMA16816(acc[mt][nt], al[mt], bh[nt]);
                }
        }
        __syncthreads();
    }

    // Epilogue: acc fragment -> bias + relu -> gmem
    int row0 = blockIdx.y * 128 + warpM + (lane >> 2);
    int col0 = blockIdx.x * 128 + warpN + (lane & 3) * 2;
#pragma unroll
    for (int mt = 0; mt < 4; mt++) {
#pragma unroll
        for (int nt = 0; nt < 4; nt++) {
            int r = row0 + mt * 16;
            int cc = col0 + nt * 8;
            float b0 = bias[cc], b1 = bias[cc + 1];
            float2 d0, d1;
            d0.x = acc[mt][nt][0] + b0; d0.y = acc[mt][nt][1] + b1;
            d1.x = acc[mt][nt][2] + b0; d1.y = acc[mt][nt][3] + b1;
            if (ACT) {
                d0.x = fmaxf(d0.x, 0.f); d0.y = fmaxf(d0.y, 0.f);
                d1.x = fmaxf(d1.x, 0.f); d1.y = fmaxf(d1.y, 0.f);
            }
            *(float2*)(C + (size_t)r * 512 + cc)       = d0;
            *(float2*)(C + (size_t)(r + 8) * 512 + cc) = d1;
        }
    }
}

// ---------------------------------------------------------------------------
// Fused causal attention with online softmax (unchanged).
// ---------------------------------------------------------------------------
__global__ void __launch_bounds__(128)
attn_kernel(const int* __restrict__ kpm) {
    __shared__ float ks[64][64];
    __shared__ float vs[64][64];

    int bid = blockIdx.x;
    int h = bid & 7;
    int n = (bid >> 3) % N_;
    int b = bid / (H_ * N_);
    int tq = threadIdx.x;
    int L  = kpm[b];

    size_t base = ((size_t)(b * T_) * N_ + n) * D_ + h * DH;
    const size_t rstride = (size_t)N_ * D_;

    float qr[DH], acc[DH];
    const float* qp = g_q + base + (size_t)tq * rstride;
#pragma unroll
    for (int d = 0; d < DH; d += 4) {
        float4 t4 = *(const float4*)(qp + d);
        qr[d] = t4.x; qr[d + 1] = t4.y; qr[d + 2] = t4.z; qr[d + 3] = t4.w;
    }
#pragma unroll
    for (int d = 0; d < DH; d++) acc[d] = 0.f;

    float m = -CUDART_INF_F, l = 0.f;
    int pmax = min(tq, L - 1);

    for (int c0 = 0; c0 < T_; c0 += 64) {
        __syncthreads();
#pragma unroll
        for (int e = threadIdx.x * 4; e < 64 * 64; e += 128 * 4) {
            int r = e >> 6, d = e & 63;
            size_t off = base + (size_t)(c0 + r) * rstride + d;
            *(float4*)&ks[r][d] = *(const float4*)(g_k + off);
            *(float4*)&vs[r][d] = *(const float4*)(g_v + off);
        }
        __syncthreads();

        int pend = min(pmax, c0 + 63);
        for (int p = c0; p <= pend; p++) {
            const float* kr = ks[p - c0];
            float s = 0.f;
#pragma unroll
            for (int d = 0; d < DH; d++) s += qr[d] * kr[d];
            s *= 0.125f;

            float mn   = fmaxf(m, s);
            float corr = __expf(m - mn);
            float e1   = __expf(s - mn);
            l = l * corr + e1;
            const float* vr = vs[p - c0];
#pragma unroll
            for (int d = 0; d < DH; d++)
                acc[d] = acc[d] * corr + e1 * vr[d];
            m = mn;
        }
    }

    float inv = 1.f / l;
    float* op = g_attn + base + (size_t)tq * rstride;
#pragma unroll
    for (int d = 0; d < DH; d += 4) {
        float4 o;
        o.x = acc[d] * inv; o.y = acc[d + 1] * inv;
        o.z = acc[d + 2] * inv; o.w = acc[d + 3] * inv;
        *(float4*)(op + d) = o;
    }
}

// ---------------------------------------------------------------------------
extern "C" void kernel_launch(void* const* d_in, const int* in_sizes, int n_in,
                              void* d_out, int out_size) {
    const float* X   = (const float*)d_in[0];
    const float* TLE = (const float*)d_in[1];
    const int*   kpm = (const int*)  d_in[2];
    const float* Wq  = (const float*)d_in[3];
    const float* bq  = (const float*)d_in[4];
    const float* Wk  = (const float*)d_in[5];
    const float* bk  = (const float*)d_in[6];
    const float* Wv  = (const float*)d_in[7];
    const float* bv  = (const float*)d_in[8];
    const float* W1  = (const float*)d_in[9];
    const float* b1  = (const float*)d_in[10];
    const float* W2  = (const float*)d_in[11];
    const float* b2  = (const float*)d_in[12];
    float* out = (float*)d_out;

    __nv_bfloat16 *pAhi, *pAlo, *pWhi, *pWlo;
    float *pq, *pk, *pv, *pa, *pm;
    cudaGetSymbolAddress((void**)&pAhi, g_Ahi);
    cudaGetSymbolAddress((void**)&pAlo, g_Alo);
    cudaGetSymbolAddress((void**)&pWhi, g_Wthi);
    cudaGetSymbolAddress((void**)&pWlo, g_Wtlo);
    cudaGetSymbolAddress((void**)&pq, g_q);
    cudaGetSymbolAddress((void**)&pk, g_k);
    cudaGetSymbolAddress((void**)&pv, g_v);
    cudaGetSymbolAddress((void**)&pa, g_attn);
    cudaGetSymbolAddress((void**)&pm, g_mid);

    cudaFuncSetAttribute(mma_gemm_kernel<1>,
                         cudaFuncAttributeMaxDynamicSharedMemorySize, SMEM_BYTES);
    cudaFuncSetAttribute(mma_gemm_kernel<0>,
                         cudaFuncAttributeMaxDynamicSharedMemorySize, SMEM_BYTES);

    // 1. split H = [X, TLE] into bf16 hi/lo
    conv_H_kernel<<<(size_t)TOK * K3 / 8 / 256, 256>>>(X, TLE);

    // 2. transpose + split weights
    wtrans_kernel<<<(512 * K3 + 255) / 256, 256>>>(Wq, pWhi + WOFF_Q, pWlo + WOFF_Q, K3);
    wtrans_kernel<<<(512 * K3 + 255) / 256, 256>>>(Wk, pWhi + WOFF_K, pWlo + WOFF_K, K3);
    wtrans_kernel<<<(512 * K3 + 255) / 256, 256>>>(Wv, pWhi + WOFF_V, pWlo + WOFF_V, K3);
    wtrans_kernel<<<(512 * D_ + 255) / 256, 256>>>(W1, pWhi + WOFF_1, pWlo + WOFF_1, D_);
    wtrans_kernel<<<(512 * D_ + 255) / 256, 256>>>(W2, pWhi + WOFF_2, pWlo + WOFF_2, D_);

    // 3. QKV projections on tensor cores (relu epilogue)
    dim3 gg(4, TOK / 128);   // (4, 800)
    mma_gemm_kernel<1><<<gg, 256, SMEM_BYTES>>>(pAhi, pAlo, pWhi + WOFF_Q, pWlo + WOFF_Q, bq, pq, K3);
    mma_gemm_kernel<1><<<gg, 256, SMEM_BYTES>>>(pAhi, pAlo, pWhi + WOFF_K, pWlo + WOFF_K, bk, pk, K3);
    mma_gemm_kernel<1><<<gg, 256, SMEM_BYTES>>>(pAhi, pAlo, pWhi + WOFF_V, pWlo + WOFF_V, bv, pv, K3);

    // 4. fused causal attention (fp32 SIMT)
    attn_kernel<<<B_ * N_ * H_, 128>>>(kpm);

    // 5. FFN on tensor cores
    conv_split_kernel<<<(size_t)TOK * D_ / 8 / 256, 256>>>(pa);
    mma_gemm_kernel<1><<<gg, 256, SMEM_BYTES>>>(pAhi, pAlo, pWhi + WOFF_1, pWlo + WOFF_1, b1, pm, D_);
    conv_split_kernel<<<(size_t)TOK * D_ / 8 / 256, 256>>>(pm);
    mma_gemm_kernel<0><<<gg, 256, SMEM_BYTES>>>(pAhi, pAlo, pWhi + WOFF_2, pWlo + WOFF_2, b2, out, D_);
}

// round 4
// speedup vs baseline: 3.4272x; 1.3437x over previous
#include <cuda_runtime.h>
#include <cuda_fp16.h>
#include <math_constants.h>
#include <cstdint>

// Problem constants
#define B_   16
#define T_   128
#define N_   50
#define D_   512
#define H_   8
#define DH   64
#define TOK  (B_ * T_ * N_)      // 102400 tokens
#define K3   (3 * D_)            // 1536

// ---------------------------------------------------------------------------
// Scratch (device globals: allocation-free per harness rules)
// ---------------------------------------------------------------------------
// Activations, fp16. Holds H=[X,TLE] (stride 1536) for QKV; later reused:
//   region0 = attn output (stride 512), region1 = FFN mid (stride 512).
__device__ __half g_Act[(size_t)TOK * K3];
__device__ float g_q[(size_t)TOK * D_];
__device__ float g_k[(size_t)TOK * D_];
__device__ float g_v[(size_t)TOK * D_];
// Combined transposed weights, fp16 hi+lo:
//   rows 0..1535 x K=1536 : [Wq;Wk;Wv]   (offset 0)
//   W1 [512x512] at WOFF1, W2 at WOFF2
#define WOFF1 2359296
#define WOFF2 2621440
__device__ __half g_Wh[2883584];
__device__ __half g_Wl[2883584];

// ---------------------------------------------------------------------------
// helpers
// ---------------------------------------------------------------------------
__device__ __forceinline__ uint32_t smem_u32(const void* p) {
    uint32_t a;
    asm("{ .reg .u64 t; cvta.to.shared.u64 t, %1; cvt.u32.u64 %0, t; }"
        : "=r"(a) : "l"(p));
    return a;
}

#define LDSM_X4(r0, r1, r2, r3, addr)                                         \
    asm volatile("ldmatrix.sync.aligned.m8n8.x4.shared.b16 {%0,%1,%2,%3}, [%4];" \
                 : "=r"(r0), "=r"(r1), "=r"(r2), "=r"(r3) : "r"(addr))

#define MMA16816(d, a, b)                                                     \
    asm volatile("mma.sync.aligned.m16n8k16.row.col.f32.f16.f16.f32 "         \
                 "{%0,%1,%2,%3}, {%4,%5,%6,%7}, {%8,%9}, {%0,%1,%2,%3};"      \
                 : "+f"((d)[0]), "+f"((d)[1]), "+f"((d)[2]), "+f"((d)[3])     \
                 : "r"((a)[0]), "r"((a)[1]), "r"((a)[2]), "r"((a)[3]),        \
                   "r"((b)[0]), "r"((b)[1]))

// ---------------------------------------------------------------------------
// H = concat(X, TLE) -> fp16, 8 elems/thread
// ---------------------------------------------------------------------------
__global__ void conv_H_kernel(const float* __restrict__ X,
                              const float* __restrict__ TLE) {
    size_t i = ((size_t)blockIdx.x * 256 + threadIdx.x) * 8;
    size_t tok = i / K3;
    int c = (int)(i % K3);
    const float* src = (c < D_) ? (X + tok * D_ + c)
                                : (TLE + tok * (size_t)(2 * D_) + (c - D_));
    float4 a = *(const float4*)src;
    float4 b = *(const float4*)(src + 4);
    float f[8] = {a.x, a.y, a.z, a.w, b.x, b.y, b.z, b.w};
    __half h[8];
#pragma unroll
    for (int j = 0; j < 8; j++) h[j] = __float2half_rn(f[j]);
    *(uint4*)(g_Act + i) = *(uint4*)h;
}

// W [K,512] fp32 -> Wt [512,K] fp16 hi/lo (dest pointers pre-offset)
__global__ void wtrans_kernel(const float* __restrict__ W,
                              __half* __restrict__ hi,
                              __half* __restrict__ lo, int K) {
    int idx = blockIdx.x * 256 + threadIdx.x;
    if (idx >= 512 * K) return;
    int n = idx / K, k = idx - n * K;
    float v = W[(size_t)k * 512 + n];
    __half h = __float2half_rn(v);
    hi[idx] = h;
    lo[idx] = __float2half_rn(v - __half2float(h));
}

// ---------------------------------------------------------------------------
// Tensor-core GEMM (HMMA fp16): C[*,512] = act(A @ Wt^T + bias)
//   A fp16 row-major [M,KDIM]; Wt fp16 hi+lo [rows,KDIM] K-major (col-major B).
//   Weights exact (hi+lo -> 2 MMAs); only A carries fp16 rounding error.
//   CTA 128x128, BK=64, 8 warps (2x4), warp tile 64x32, 3-stage cp.async.
//   QKV fusion: blockIdx.x selects among (bias0,C0)/(bias1,C1)/(bias2,C2)
//   in groups of 4 column-blocks (weights rows are [Wq;Wk;Wv] stacked).
// ---------------------------------------------------------------------------
#define BK       64
#define PSTR     72                        // halves per padded row (144 B)
#define ARR_B    (128 * PSTR * 2)          // 18432
#define STAGE_B  (3 * ARR_B)               // 55296 (A, Bh, Bl)
#define NSTAGE   3
#define SMEM_B   (NSTAGE * STAGE_B)        // 165888

template<int ACT, int HOUT, int KDIM>
__global__ void __launch_bounds__(256)
mma_gemm(const __half* __restrict__ A,
         const __half* __restrict__ Bh, const __half* __restrict__ Bl,
         const float* __restrict__ bias0, const float* __restrict__ bias1,
         const float* __restrict__ bias2,
         void* C0, void* C1, void* C2) {
    extern __shared__ char sm[];
    uint32_t sbase = smem_u32(sm);

    int tid = threadIdx.x, wid = tid >> 5, lane = tid & 31;
    int bx = blockIdx.x;
    int warpM = (wid >> 2) * 64;           // 0 or 64
    int warpN = (wid & 3) * 32;            // 0,32,64,96

    const __half* srcs[3] = {
        A  + (size_t)blockIdx.y * 128 * KDIM,
        Bh + (size_t)bx * 128 * KDIM,
        Bl + (size_t)bx * 128 * KDIM
    };

    float acc[4][4][4];
#pragma unroll
    for (int i = 0; i < 4; i++)
#pragma unroll
        for (int j = 0; j < 4; j++)
#pragma unroll
            for (int e = 0; e < 4; e++) acc[i][j][e] = 0.f;

    // copy: 3 arrays x 128 rows x 8 x 16B segments = 3072 segs, 12/thread
    auto issue = [&](int c) {
        uint32_t stb = sbase + (uint32_t)((c % NSTAGE) * STAGE_B);
        int k0 = c * BK;
#pragma unroll
        for (int j = 0; j < 12; j++) {
            int idx = tid + j * 256;
            int arr = idx >> 10, rem = idx & 1023;
            int r = rem >> 3, s = rem & 7;
            const __half* g = srcs[arr] + (size_t)r * KDIM + k0 + s * 8;
            uint32_t d = stb + (uint32_t)(arr * ARR_B + r * (PSTR * 2) + s * 16);
            asm volatile("cp.async.cg.shared.global [%0], [%1], 16;"
                         :: "r"(d), "l"(g));
        }
        asm volatile("cp.async.commit_group;");
    };

    // ldmatrix lane offsets within a stage
    uint32_t aoff = (uint32_t)((warpM + (lane & 15)) * (PSTR * 2) + (lane >> 4) * 16);
    uint32_t boff = (uint32_t)(ARR_B +
                    (warpN + ((lane >> 4) << 3) + (lane & 7)) * (PSTR * 2) +
                    ((lane >> 3) & 1) * 16);

    const int nch = KDIM / BK;
    issue(0);
    issue(1);
    for (int c = 0; c < nch; c++) {
        if (c + 2 < nch) {
            issue(c + 2);
            asm volatile("cp.async.wait_group 2;");
        } else if (c + 1 < nch) {
            asm volatile("cp.async.wait_group 1;");
        } else {
            asm volatile("cp.async.wait_group 0;");
        }
        __syncthreads();

        uint32_t stage = sbase + (uint32_t)((c % NSTAGE) * STAGE_B);
#pragma unroll
        for (int kk = 0; kk < 4; kk++) {
            uint32_t ah[4][4];
#pragma unroll
            for (int mt = 0; mt < 4; mt++) {
                uint32_t ad = stage + aoff + mt * (16 * PSTR * 2) + kk * 32;
                LDSM_X4(ah[mt][0], ah[mt][1], ah[mt][2], ah[mt][3], ad);
            }
            uint32_t bh[4][2], bl[4][2];
#pragma unroll
            for (int np = 0; np < 2; np++) {
                uint32_t bd = stage + boff + np * (16 * PSTR * 2) + kk * 32;
                LDSM_X4(bh[2*np][0], bh[2*np][1], bh[2*np+1][0], bh[2*np+1][1], bd);
                LDSM_X4(bl[2*np][0], bl[2*np][1], bl[2*np+1][0], bl[2*np+1][1],
                        bd + ARR_B);
            }
#pragma unroll
            for (int mt = 0; mt < 4; mt++)
#pragma unroll
                for (int nt = 0; nt < 4; nt++) {
                    MMA16816(acc[mt][nt], ah[mt], bh[nt]);
                    MMA16816(acc[mt][nt], ah[mt], bl[nt]);
                }
        }
        __syncthreads();
    }

    // Epilogue: bias + (relu) -> fp32 or fp16 store. Output stride is 512.
    const float* bias = (bx < 4) ? bias0 : (bx < 8) ? bias1 : bias2;
    void* Cp          = (bx < 4) ? C0    : (bx < 8) ? C1    : C2;
    int row0 = blockIdx.y * 128 + warpM + (lane >> 2);
    int col0 = (bx & 3) * 128 + warpN + (lane & 3) * 2;
#pragma unroll
    for (int mt = 0; mt < 4; mt++) {
#pragma unroll
        for (int nt = 0; nt < 4; nt++) {
            int r = row0 + mt * 16;
            int cc = col0 + nt * 8;
            float b0 = bias[cc], b1 = bias[cc + 1];
            float2 d0, d1;
            d0.x = acc[mt][nt][0] + b0; d0.y = acc[mt][nt][1] + b1;
            d1.x = acc[mt][nt][2] + b0; d1.y = acc[mt][nt][3] + b1;
            if (ACT) {
                d0.x = fmaxf(d0.x, 0.f); d0.y = fmaxf(d0.y, 0.f);
                d1.x = fmaxf(d1.x, 0.f); d1.y = fmaxf(d1.y, 0.f);
            }
            if (HOUT) {
                __half* Ch = (__half*)Cp;
                *(__half2*)(Ch + (size_t)r * 512 + cc)       = __floats2half2_rn(d0.x, d0.y);
                *(__half2*)(Ch + (size_t)(r + 8) * 512 + cc) = __floats2half2_rn(d1.x, d1.y);
            } else {
                float* Cf = (float*)Cp;
                *(float2*)(Cf + (size_t)r * 512 + cc)       = d0;
                *(float2*)(Cf + (size_t)(r + 8) * 512 + cc) = d1;
            }
        }
    }
}

// ---------------------------------------------------------------------------
// Fused causal attention with online softmax; writes fp16 output.
// One block per (b, n, head): 128 threads, one query row each.
// ---------------------------------------------------------------------------
__global__ void __launch_bounds__(128)
attn_kernel(const int* __restrict__ kpm, __half* __restrict__ outp) {
    __shared__ float ks[64][64];
    __shared__ float vs[64][64];

    int bid = blockIdx.x;
    int h = bid & 7;
    int n = (bid >> 3) % N_;
    int b = bid / (H_ * N_);
    int tq = threadIdx.x;
    int L  = kpm[b];

    size_t base = ((size_t)(b * T_) * N_ + n) * D_ + h * DH;
    const size_t rstride = (size_t)N_ * D_;

    float qr[DH], acc[DH];
    const float* qp = g_q + base + (size_t)tq * rstride;
#pragma unroll
    for (int d = 0; d < DH; d += 4) {
        float4 t4 = *(const float4*)(qp + d);
        qr[d] = t4.x; qr[d + 1] = t4.y; qr[d + 2] = t4.z; qr[d + 3] = t4.w;
    }
#pragma unroll
    for (int d = 0; d < DH; d++) acc[d] = 0.f;

    float m = -CUDART_INF_F, l = 0.f;
    int pmax = min(tq, L - 1);

    for (int c0 = 0; c0 < T_; c0 += 64) {
        __syncthreads();
#pragma unroll
        for (int e = threadIdx.x * 4; e < 64 * 64; e += 128 * 4) {
            int r = e >> 6, d = e & 63;
            size_t off = base + (size_t)(c0 + r) * rstride + d;
            *(float4*)&ks[r][d] = *(const float4*)(g_k + off);
            *(float4*)&vs[r][d] = *(const float4*)(g_v + off);
        }
        __syncthreads();

        int pend = min(pmax, c0 + 63);
        for (int p = c0; p <= pend; p++) {
            const float* kr = ks[p - c0];
            float s0 = 0.f, s1 = 0.f, s2 = 0.f, s3 = 0.f;
#pragma unroll
            for (int d = 0; d < DH; d += 4) {
                s0 += qr[d]     * kr[d];
                s1 += qr[d + 1] * kr[d + 1];
                s2 += qr[d + 2] * kr[d + 2];
                s3 += qr[d + 3] * kr[d + 3];
            }
            float s = ((s0 + s1) + (s2 + s3)) * 0.125f;

            float mn   = fmaxf(m, s);
            float corr = __expf(m - mn);
            float e1   = __expf(s - mn);
            l = l * corr + e1;
            const float* vr = vs[p - c0];
#pragma unroll
            for (int d = 0; d < DH; d++)
                acc[d] = acc[d] * corr + e1 * vr[d];
            m = mn;
        }
    }

    float inv = 1.f / l;
    __half* op = outp + base + (size_t)tq * rstride;
#pragma unroll
    for (int d = 0; d < DH; d += 2)
        *(__half2*)(op + d) = __floats2half2_rn(acc[d] * inv, acc[d + 1] * inv);
}

// ---------------------------------------------------------------------------
extern "C" void kernel_launch(void* const* d_in, const int* in_sizes, int n_in,
                              void* d_out, int out_size) {
    const float* X   = (const float*)d_in[0];
    const float* TLE = (const float*)d_in[1];
    const int*   kpm = (const int*)  d_in[2];
    const float* Wq  = (const float*)d_in[3];
    const float* bq  = (const float*)d_in[4];
    const float* Wk  = (const float*)d_in[5];
    const float* bk  = (const float*)d_in[6];
    const float* Wv  = (const float*)d_in[7];
    const float* bv  = (const float*)d_in[8];
    const float* W1  = (const float*)d_in[9];
    const float* b1  = (const float*)d_in[10];
    const float* W2  = (const float*)d_in[11];
    const float* b2  = (const float*)d_in[12];
    float* out = (float*)d_out;

    __half *pAct, *pWh, *pWl;
    float *pq, *pk, *pv;
    cudaGetSymbolAddress((void**)&pAct, g_Act);
    cudaGetSymbolAddress((void**)&pWh, g_Wh);
    cudaGetSymbolAddress((void**)&pWl, g_Wl);
    cudaGetSymbolAddress((void**)&pq, g_q);
    cudaGetSymbolAddress((void**)&pk, g_k);
    cudaGetSymbolAddress((void**)&pv, g_v);

    __half* actR0 = pAct;                       // attn out / W1 input
    __half* actR1 = pAct + (size_t)TOK * D_;    // FFN mid

    cudaFuncSetAttribute(mma_gemm<1,0,1536>,
                         cudaFuncAttributeMaxDynamicSharedMemorySize, SMEM_B);
    cudaFuncSetAttribute(mma_gemm<1,1,512>,
                         cudaFuncAttributeMaxDynamicSharedMemorySize, SMEM_B);
    cudaFuncSetAttribute(mma_gemm<0,0,512>,
                         cudaFuncAttributeMaxDynamicSharedMemorySize, SMEM_B);

    // 1. H = [X, TLE] -> fp16
    conv_H_kernel<<<(size_t)TOK * K3 / 8 / 256, 256>>>(X, TLE);

    // 2. transpose + hi/lo split weights (combined layout)
    wtrans_kernel<<<3072, 256>>>(Wq, pWh,                    pWl,                    K3);
    wtrans_kernel<<<3072, 256>>>(Wk, pWh + (size_t)512 * K3, pWl + (size_t)512 * K3, K3);
    wtrans_kernel<<<3072, 256>>>(Wv, pWh + (size_t)1024 * K3, pWl + (size_t)1024 * K3, K3);
    wtrans_kernel<<<1024, 256>>>(W1, pWh + WOFF1, pWl + WOFF1, D_);
    wtrans_kernel<<<1024, 256>>>(W2, pWh + WOFF2, pWl + WOFF2, D_);

    // 3. fused QKV projection (one launch, 12 column blocks)
    mma_gemm<1,0,1536><<<dim3(12, TOK / 128), 256, SMEM_B>>>(
        pAct, pWh, pWl, bq, bk, bv, pq, pk, pv);

    // 4. fused causal attention -> fp16 region0
    attn_kernel<<<B_ * N_ * H_, 128>>>(kpm, actR0);

    // 5. FFN: W1 (relu, fp16 out to region1), W2 (fp32 out to d_out)
    mma_gemm<1,1,512><<<dim3(4, TOK / 128), 256, SMEM_B>>>(
        actR0, pWh + WOFF1, pWl + WOFF1, b1, b1, b1, actR1, actR1, actR1);
    mma_gemm<0,0,512><<<dim3(4, TOK / 128), 256, SMEM_B>>>(
        actR1, pWh + WOFF2, pWl + WOFF2, b2, b2, b2, out, out, out);
}

// round 5
// speedup vs baseline: 5.2021x; 1.5179x over previous
#include <cuda_runtime.h>
#include <cuda_fp16.h>
#include <math_constants.h>
#include <cstdint>

// Problem constants
#define B_   16
#define T_   128
#define N_   50
#define D_   512
#define H_   8
#define DH   64
#define TOK  (B_ * T_ * N_)      // 102400 tokens
#define K3   (3 * D_)            // 1536

typedef unsigned long long ull;

// ---------------------------------------------------------------------------
// Scratch (device globals: allocation-free per harness rules)
// ---------------------------------------------------------------------------
// fp16 activations. Holds H=[X,TLE] (stride 1536) for QKV; later reused:
//   region0 = attn output (stride 512), region1 = FFN mid (stride 512).
__device__ __half g_Act[(size_t)TOK * K3];
__device__ __half g_q[(size_t)TOK * D_];
__device__ __half g_k[(size_t)TOK * D_];
__device__ __half g_v[(size_t)TOK * D_];
// Transposed weights fp16: [Wq;Wk;Wv] stacked (1536 rows x K=1536), then W1, W2.
#define WOFF1 2359296
#define WOFF2 2621440
__device__ __half g_Wh[2883584];
__device__ __half g_Wl[2883584];        // lo only populated for W1/W2

// ---------------------------------------------------------------------------
// helpers
// ---------------------------------------------------------------------------
__device__ __forceinline__ uint32_t smem_u32(const void* p) {
    uint32_t a;
    asm("{ .reg .u64 t; cvta.to.shared.u64 t, %1; cvt.u32.u64 %0, t; }"
        : "=r"(a) : "l"(p));
    return a;
}

#define LDSM_X4(r0, r1, r2, r3, addr)                                         \
    asm volatile("ldmatrix.sync.aligned.m8n8.x4.shared.b16 {%0,%1,%2,%3}, [%4];" \
                 : "=r"(r0), "=r"(r1), "=r"(r2), "=r"(r3) : "r"(addr))

#define MMA16816(d, a, b)                                                     \
    asm volatile("mma.sync.aligned.m16n8k16.row.col.f32.f16.f16.f32 "         \
                 "{%0,%1,%2,%3}, {%4,%5,%6,%7}, {%8,%9}, {%0,%1,%2,%3};"      \
                 : "+f"((d)[0]), "+f"((d)[1]), "+f"((d)[2]), "+f"((d)[3])     \
                 : "r"((a)[0]), "r"((a)[1]), "r"((a)[2]), "r"((a)[3]),        \
                   "r"((b)[0]), "r"((b)[1]))

// packed f32x2 (sm_100+ base ISA)
#define FMA2(d, a, b, c) \
    asm("fma.rn.f32x2 %0, %1, %2, %3;" : "=l"(d) : "l"(a), "l"(b), "l"(c))
#define MUL2(d, a, b) \
    asm("mul.rn.f32x2 %0, %1, %2;" : "=l"(d) : "l"(a), "l"(b))
#define ADD2(d, a, b) \
    asm("add.rn.f32x2 %0, %1, %2;" : "=l"(d) : "l"(a), "l"(b))

__device__ __forceinline__ ull bcast2(float f) {
    uint32_t u = __float_as_uint(f);
    return (ull)u | ((ull)u << 32);
}

// ---------------------------------------------------------------------------
// H = concat(X, TLE) -> fp16, 8 elems/thread
// ---------------------------------------------------------------------------
__global__ void conv_H_kernel(const float* __restrict__ X,
                              const float* __restrict__ TLE) {
    size_t i = ((size_t)blockIdx.x * 256 + threadIdx.x) * 8;
    size_t tok = i / K3;
    int c = (int)(i % K3);
    const float* src = (c < D_) ? (X + tok * D_ + c)
                                : (TLE + tok * (size_t)(2 * D_) + (c - D_));
    float4 a = *(const float4*)src;
    float4 b = *(const float4*)(src + 4);
    float f[8] = {a.x, a.y, a.z, a.w, b.x, b.y, b.z, b.w};
    __half h[8];
#pragma unroll
    for (int j = 0; j < 8; j++) h[j] = __float2half_rn(f[j]);
    *(uint4*)(g_Act + i) = *(uint4*)h;
}

// W [K,512] fp32 -> Wt [512,K] fp16 (optionally also lo residual)
__global__ void wtrans_kernel(const float* __restrict__ W,
                              __half* __restrict__ hi,
                              __half* __restrict__ lo, int K, int write_lo) {
    int idx = blockIdx.x * 256 + threadIdx.x;
    if (idx >= 512 * K) return;
    int n = idx / K, k = idx - n * K;
    float v = W[(size_t)k * 512 + n];
    __half h = __float2half_rn(v);
    hi[idx] = h;
    if (write_lo) lo[idx] = __float2half_rn(v - __half2float(h));
}

// ---------------------------------------------------------------------------
// Tensor-core GEMM (HMMA fp16): C[*,512] = act(A @ Wt^T + bias)
//   NB=1: plain fp16 weights (QKV). NB=2: exact hi+lo weights (FFN).
//   CTA 128x128, BK=64, 8 warps (2x4), warp tile 64x32, 3-stage cp.async.
//   QKV fusion via blockIdx.x: groups of 4 column-blocks -> (bias_i, C_i).
// ---------------------------------------------------------------------------
#define BK       64
#define PSTR     72                        // halves per padded row (144 B)
#define ARR_B    (128 * PSTR * 2)          // 18432
#define NSTAGE   3

template<int ACT, int HOUT, int KDIM, int NB>
__global__ void __launch_bounds__(256)
mma_gemm(const __half* __restrict__ A,
         const __half* __restrict__ Bh, const __half* __restrict__ Bl,
         const float* __restrict__ bias0, const float* __restrict__ bias1,
         const float* __restrict__ bias2,
         void* C0, void* C1, void* C2) {
    const int STAGE_B = (1 + NB) * ARR_B;
    extern __shared__ char sm[];
    uint32_t sbase = smem_u32(sm);

    int tid = threadIdx.x, wid = tid >> 5, lane = tid & 31;
    int bx = blockIdx.x;
    int warpM = (wid >> 2) * 64;           // 0 or 64
    int warpN = (wid & 3) * 32;            // 0,32,64,96

    const __half* srcs[1 + NB];
    srcs[0] = A + (size_t)blockIdx.y * 128 * KDIM;
    srcs[1] = Bh + (size_t)bx * 128 * KDIM;
    if (NB == 2) srcs[2] = Bl + (size_t)bx * 128 * KDIM;

    float acc[4][4][4];
#pragma unroll
    for (int i = 0; i < 4; i++)
#pragma unroll
        for (int j = 0; j < 4; j++)
#pragma unroll
            for (int e = 0; e < 4; e++) acc[i][j][e] = 0.f;

    // copy: (1+NB) arrays x 128 rows x 8 x 16B segs; (1+NB)*4 per thread
    auto issue = [&](int c) {
        uint32_t stb = sbase + (uint32_t)((c % NSTAGE) * STAGE_B);
        int k0 = c * BK;
#pragma unroll
        for (int j = 0; j < (1 + NB) * 4; j++) {
            int idx = tid + j * 256;
            int arr = idx >> 10, rem = idx & 1023;
            int r = rem >> 3, s = rem & 7;
            const __half* g = srcs[arr] + (size_t)r * KDIM + k0 + s * 8;
            uint32_t d = stb + (uint32_t)(arr * ARR_B + r * (PSTR * 2) + s * 16);
            asm volatile("cp.async.cg.shared.global [%0], [%1], 16;"
                         :: "r"(d), "l"(g));
        }
        asm volatile("cp.async.commit_group;");
    };

    uint32_t aoff = (uint32_t)((warpM + (lane & 15)) * (PSTR * 2) + (lane >> 4) * 16);
    uint32_t boff = (uint32_t)(ARR_B +
                    (warpN + ((lane >> 4) << 3) + (lane & 7)) * (PSTR * 2) +
                    ((lane >> 3) & 1) * 16);

    const int nch = KDIM / BK;
    issue(0);
    issue(1);
    for (int c = 0; c < nch; c++) {
        if (c + 2 < nch) {
            issue(c + 2);
            asm volatile("cp.async.wait_group 2;");
        } else if (c + 1 < nch) {
            asm volatile("cp.async.wait_group 1;");
        } else {
            asm volatile("cp.async.wait_group 0;");
        }
        __syncthreads();

        uint32_t stage = sbase + (uint32_t)((c % NSTAGE) * STAGE_B);
#pragma unroll
        for (int kk = 0; kk < 4; kk++) {
            uint32_t ah[4][4];
#pragma unroll
            for (int mt = 0; mt < 4; mt++) {
                uint32_t ad = stage + aoff + mt * (16 * PSTR * 2) + kk * 32;
                LDSM_X4(ah[mt][0], ah[mt][1], ah[mt][2], ah[mt][3], ad);
            }
            uint32_t bh[4][2], bl[4][2];
#pragma unroll
            for (int np = 0; np < 2; np++) {
                uint32_t bd = stage + boff + np * (16 * PSTR * 2) + kk * 32;
                LDSM_X4(bh[2*np][0], bh[2*np][1], bh[2*np+1][0], bh[2*np+1][1], bd);
                if (NB == 2)
                    LDSM_X4(bl[2*np][0], bl[2*np][1], bl[2*np+1][0], bl[2*np+1][1],
                            bd + ARR_B);
            }
#pragma unroll
            for (int mt = 0; mt < 4; mt++)
#pragma unroll
                for (int nt = 0; nt < 4; nt++) {
                    MMA16816(acc[mt][nt], ah[mt], bh[nt]);
                    if (NB == 2) MMA16816(acc[mt][nt], ah[mt], bl[nt]);
                }
        }
        __syncthreads();
    }

    // Epilogue: bias + (relu) -> fp32 or fp16 store. Output stride is 512.
    const float* bias = (bx < 4) ? bias0 : (bx < 8) ? bias1 : bias2;
    void* Cp          = (bx < 4) ? C0    : (bx < 8) ? C1    : C2;
    int row0 = blockIdx.y * 128 + warpM + (lane >> 2);
    int col0 = (bx & 3) * 128 + warpN + (lane & 3) * 2;
#pragma unroll
    for (int mt = 0; mt < 4; mt++) {
#pragma unroll
        for (int nt = 0; nt < 4; nt++) {
            int r = row0 + mt * 16;
            int cc = col0 + nt * 8;
            float b0 = bias[cc], b1 = bias[cc + 1];
            float2 d0, d1;
            d0.x = acc[mt][nt][0] + b0; d0.y = acc[mt][nt][1] + b1;
            d1.x = acc[mt][nt][2] + b0; d1.y = acc[mt][nt][3] + b1;
            if (ACT) {
                d0.x = fmaxf(d0.x, 0.f); d0.y = fmaxf(d0.y, 0.f);
                d1.x = fmaxf(d1.x, 0.f); d1.y = fmaxf(d1.y, 0.f);
            }
            if (HOUT) {
                __half* Ch = (__half*)Cp;
                *(__half2*)(Ch + (size_t)r * 512 + cc)       = __floats2half2_rn(d0.x, d0.y);
                *(__half2*)(Ch + (size_t)(r + 8) * 512 + cc) = __floats2half2_rn(d1.x, d1.y);
            } else {
                float* Cf = (float*)Cp;
                *(float2*)(Cf + (size_t)r * 512 + cc)       = d0;
                *(float2*)(Cf + (size_t)(r + 8) * 512 + cc) = d1;
            }
        }
    }
}

// ---------------------------------------------------------------------------
// Fused causal attention, online softmax, packed f32x2 math.
// One block per (b, n, head): 128 threads, one query row each.
// q/k/v fp16 in gmem; K/V staged to fp32 smem; output fp16.
// ---------------------------------------------------------------------------
__global__ void __launch_bounds__(128)
attn_kernel(const int* __restrict__ kpm,
            const __half* __restrict__ Q, const __half* __restrict__ Kp,
            const __half* __restrict__ V, __half* __restrict__ outp) {
    __shared__ float ks[64][64];
    __shared__ float vs[64][64];

    int bid = blockIdx.x;
    int h = bid & 7;
    int n = (bid >> 3) % N_;
    int b = bid / (H_ * N_);
    int tq = threadIdx.x;
    int L  = kpm[b];

    size_t base = ((size_t)(b * T_) * N_ + n) * D_ + h * DH;
    const size_t rstride = (size_t)N_ * D_;

    // load q row (fp16 -> packed f32x2)
    ull qr2[32], acc2[32];
    {
        const __half* qp = Q + base + (size_t)tq * rstride;
#pragma unroll
        for (int d = 0; d < DH; d += 8) {
            uint4 u = *(const uint4*)(qp + d);
            const __half2* h2 = (const __half2*)&u;
#pragma unroll
            for (int j = 0; j < 4; j++) {
                float2 f = __half22float2(h2[j]);
                qr2[(d >> 1) + j] = (ull)__float_as_uint(f.x)
                                  | ((ull)__float_as_uint(f.y) << 32);
            }
        }
    }
#pragma unroll
    for (int j = 0; j < 32; j++) acc2[j] = 0ull;

    float m = -CUDART_INF_F, l = 0.f;
    int pmax = min(tq, L - 1);

    for (int c0 = 0; c0 < T_; c0 += 64) {
        __syncthreads();
        // cooperative load: 64 rows x 64 halves per array, fp16 -> fp32 smem
#pragma unroll
        for (int it = 0; it < 4; it++) {
            int e = (threadIdx.x + it * 128) * 8;
            int r = e >> 6, d = e & 63;
            size_t off = base + (size_t)(c0 + r) * rstride + d;
            uint4 ku = *(const uint4*)(Kp + off);
            uint4 vu = *(const uint4*)(V + off);
            const __half2* kh = (const __half2*)&ku;
            const __half2* vh = (const __half2*)&vu;
#pragma unroll
            for (int j = 0; j < 4; j++) {
                *(float2*)&ks[r][d + 2 * j] = __half22float2(kh[j]);
                *(float2*)&vs[r][d + 2 * j] = __half22float2(vh[j]);
            }
        }
        __syncthreads();

        int pend = min(pmax, c0 + 63);
        for (int p = c0; p <= pend; p++) {
            const ull* kr2 = (const ull*)ks[p - c0];
            ull s0 = 0, s1 = 0, s2 = 0, s3 = 0;
#pragma unroll
            for (int j = 0; j < 32; j += 4) {
                FMA2(s0, qr2[j],     kr2[j],     s0);
                FMA2(s1, qr2[j + 1], kr2[j + 1], s1);
                FMA2(s2, qr2[j + 2], kr2[j + 2], s2);
                FMA2(s3, qr2[j + 3], kr2[j + 3], s3);
            }
            ADD2(s0, s0, s1);
            ADD2(s2, s2, s3);
            ADD2(s0, s0, s2);
            float s = (__uint_as_float((uint32_t)s0) +
                       __uint_as_float((uint32_t)(s0 >> 32))) * 0.125f;

            float mn   = fmaxf(m, s);
            float corr = __expf(m - mn);
            float e1   = __expf(s - mn);
            l = l * corr + e1;
            ull corr2 = bcast2(corr), e12 = bcast2(e1);
            const ull* vr2 = (const ull*)vs[p - c0];
#pragma unroll
            for (int j = 0; j < 32; j++) {
                ull t;
                MUL2(t, acc2[j], corr2);
                FMA2(acc2[j], e12, vr2[j], t);
            }
            m = mn;
        }
    }

    float inv = 1.f / l;
    __half* op = outp + base + (size_t)tq * rstride;
#pragma unroll
    for (int j = 0; j < 32; j++) {
        float x = __uint_as_float((uint32_t)acc2[j]) * inv;
        float y = __uint_as_float((uint32_t)(acc2[j] >> 32)) * inv;
        *(__half2*)(op + 2 * j) = __floats2half2_rn(x, y);
    }
}

// ---------------------------------------------------------------------------
extern "C" void kernel_launch(void* const* d_in, const int* in_sizes, int n_in,
                              void* d_out, int out_size) {
    const float* X   = (const float*)d_in[0];
    const float* TLE = (const float*)d_in[1];
    const int*   kpm = (const int*)  d_in[2];
    const float* Wq  = (const float*)d_in[3];
    const float* bq  = (const float*)d_in[4];
    const float* Wk  = (const float*)d_in[5];
    const float* bk  = (const float*)d_in[6];
    const float* Wv  = (const float*)d_in[7];
    const float* bv  = (const float*)d_in[8];
    const float* W1  = (const float*)d_in[9];
    const float* b1  = (const float*)d_in[10];
    const float* W2  = (const float*)d_in[11];
    const float* b2  = (const float*)d_in[12];
    float* out = (float*)d_out;

    __half *pAct, *pWh, *pWl, *pq, *pk, *pv;
    cudaGetSymbolAddress((void**)&pAct, g_Act);
    cudaGetSymbolAddress((void**)&pWh, g_Wh);
    cudaGetSymbolAddress((void**)&pWl, g_Wl);
    cudaGetSymbolAddress((void**)&pq, g_q);
    cudaGetSymbolAddress((void**)&pk, g_k);
    cudaGetSymbolAddress((void**)&pv, g_v);

    __half* actR0 = pAct;                       // attn out / W1 input
    __half* actR1 = pAct + (size_t)TOK * D_;    // FFN mid

    const int SMEM_QKV = 2 * ARR_B * NSTAGE;    // 110592
    const int SMEM_FFN = 3 * ARR_B * NSTAGE;    // 165888
    cudaFuncSetAttribute((const void*)mma_gemm<1,1,1536,1>,
                         cudaFuncAttributeMaxDynamicSharedMemorySize, SMEM_QKV);
    cudaFuncSetAttribute((const void*)mma_gemm<1,1,512,2>,
                         cudaFuncAttributeMaxDynamicSharedMemorySize, SMEM_FFN);
    cudaFuncSetAttribute((const void*)mma_gemm<0,0,512,2>,
                         cudaFuncAttributeMaxDynamicSharedMemorySize, SMEM_FFN);

    // 1. H = [X, TLE] -> fp16
    conv_H_kernel<<<(size_t)TOK * K3 / 8 / 256, 256>>>(X, TLE);

    // 2. transpose weights (QKV: hi only; FFN: hi+lo)
    wtrans_kernel<<<3072, 256>>>(Wq, pWh,                     pWl, K3, 0);
    wtrans_kernel<<<3072, 256>>>(Wk, pWh + (size_t)512 * K3,  pWl, K3, 0);
    wtrans_kernel<<<3072, 256>>>(Wv, pWh + (size_t)1024 * K3, pWl, K3, 0);
    wtrans_kernel<<<1024, 256>>>(W1, pWh + WOFF1, pWl + WOFF1, D_, 1);
    wtrans_kernel<<<1024, 256>>>(W2, pWh + WOFF2, pWl + WOFF2, D_, 1);

    // 3. fused QKV projection (single launch; plain fp16 weights)
    mma_gemm<1,1,1536,1><<<dim3(12, TOK / 128), 256, SMEM_QKV>>>(
        pAct, pWh, pWh, bq, bk, bv, pq, pk, pv);

    // 4. fused causal attention -> fp16 region0
    attn_kernel<<<B_ * N_ * H_, 128>>>(kpm, pq, pk, pv, actR0);

    // 5. FFN with exact (hi+lo) weights
    mma_gemm<1,1,512,2><<<dim3(4, TOK / 128), 256, SMEM_FFN>>>(
        actR0, pWh + WOFF1, pWl + WOFF1, b1, b1, b1, actR1, actR1, actR1);
    mma_gemm<0,0,512,2><<<dim3(4, TOK / 128), 256, SMEM_FFN>>>(
        actR1, pWh + WOFF2, pWl + WOFF2, b2, b2, b2, out, out, out);
}

// round 6
// speedup vs baseline: 5.6838x; 1.0926x over previous
#include <cuda_runtime.h>
#include <cuda_fp16.h>
#include <math_constants.h>
#include <cstdint>

// Problem constants
#define B_   16
#define T_   128
#define N_   50
#define D_   512
#define H_   8
#define DH   64
#define TOK  (B_ * T_ * N_)      // 102400 tokens
#define K3   (3 * D_)            // 1536

typedef unsigned long long ull;

// ---------------------------------------------------------------------------
// Scratch (device globals: allocation-free per harness rules)
// ---------------------------------------------------------------------------
// fp16 activations. Holds H=[X,TLE] (stride 1536) for QKV; later reused:
//   region0 = attn output (stride 512), region1 = FFN mid (stride 512).
__device__ __half g_Act[(size_t)TOK * K3];
__device__ __half g_q[(size_t)TOK * D_];
__device__ __half g_k[(size_t)TOK * D_];
__device__ __half g_v[(size_t)TOK * D_];
// Transposed fp16 weights: [Wq;Wk;Wv] stacked (1536 rows x K=1536), then W1, W2.
#define WOFF1 2359296
#define WOFF2 2621440
__device__ __half g_Wh[2883584];

// ---------------------------------------------------------------------------
// helpers
// ---------------------------------------------------------------------------
__device__ __forceinline__ uint32_t smem_u32(const void* p) {
    uint32_t a;
    asm("{ .reg .u64 t; cvta.to.shared.u64 t, %1; cvt.u32.u64 %0, t; }"
        : "=r"(a) : "l"(p));
    return a;
}

#define LDSM_X4(r0, r1, r2, r3, addr)                                         \
    asm volatile("ldmatrix.sync.aligned.m8n8.x4.shared.b16 {%0,%1,%2,%3}, [%4];" \
                 : "=r"(r0), "=r"(r1), "=r"(r2), "=r"(r3) : "r"(addr))

#define MMA16816(d, a, b)                                                     \
    asm volatile("mma.sync.aligned.m16n8k16.row.col.f32.f16.f16.f32 "         \
                 "{%0,%1,%2,%3}, {%4,%5,%6,%7}, {%8,%9}, {%0,%1,%2,%3};"      \
                 : "+f"((d)[0]), "+f"((d)[1]), "+f"((d)[2]), "+f"((d)[3])     \
                 : "r"((a)[0]), "r"((a)[1]), "r"((a)[2]), "r"((a)[3]),        \
                   "r"((b)[0]), "r"((b)[1]))

// packed f32x2 (sm_100+ base ISA)
#define FMA2(d, a, b, c) \
    asm("fma.rn.f32x2 %0, %1, %2, %3;" : "=l"(d) : "l"(a), "l"(b), "l"(c))
#define MUL2(d, a, b) \
    asm("mul.rn.f32x2 %0, %1, %2;" : "=l"(d) : "l"(a), "l"(b))
#define ADD2(d, a, b) \
    asm("add.rn.f32x2 %0, %1, %2;" : "=l"(d) : "l"(a), "l"(b))

__device__ __forceinline__ ull bcast2(float f) {
    uint32_t u = __float_as_uint(f);
    return (ull)u | ((ull)u << 32);
}

// ---------------------------------------------------------------------------
// H = concat(X, TLE) -> fp16, 8 elems/thread
// ---------------------------------------------------------------------------
__global__ void conv_H_kernel(const float* __restrict__ X,
                              const float* __restrict__ TLE) {
    size_t i = ((size_t)blockIdx.x * 256 + threadIdx.x) * 8;
    size_t tok = i / K3;
    int c = (int)(i % K3);
    const float* src = (c < D_) ? (X + tok * D_ + c)
                                : (TLE + tok * (size_t)(2 * D_) + (c - D_));
    float4 a = *(const float4*)src;
    float4 b = *(const float4*)(src + 4);
    float f[8] = {a.x, a.y, a.z, a.w, b.x, b.y, b.z, b.w};
    __half h[8];
#pragma unroll
    for (int j = 0; j < 8; j++) h[j] = __float2half_rn(f[j]);
    *(uint4*)(g_Act + i) = *(uint4*)h;
}

// W [K,512] fp32 -> Wt [512,K] fp16
__global__ void wtrans_kernel(const float* __restrict__ W,
                              __half* __restrict__ hi, int K) {
    int idx = blockIdx.x * 256 + threadIdx.x;
    if (idx >= 512 * K) return;
    int n = idx / K, k = idx - n * K;
    hi[idx] = __float2half_rn(W[(size_t)k * 512 + n]);
}

// ---------------------------------------------------------------------------
// Tensor-core GEMM (HMMA fp16): C[*,512] = act(A @ Wt^T + bias)
//   CTA tile 128x256, 8 warps (2x4), warp tile 64x64, BK=64, 3-stage cp.async.
//   Output columns come in pairs of 256-wide blocks: reg = bx>>1 selects
//   (bias_r, C_r); (bx&1) selects the 256-col half (output stride 512).
// ---------------------------------------------------------------------------
#define BK       64
#define PSTR     72                        // halves per padded row (144 B)
#define ARR_A    (128 * PSTR * 2)          // 18432
#define ARR_Bt   (256 * PSTR * 2)          // 36864
#define STAGE_B  (ARR_A + ARR_Bt)          // 55296
#define NSTAGE   3
#define SMEM_B   (NSTAGE * STAGE_B)        // 165888

template<int ACT, int HOUT, int KDIM>
__global__ void __launch_bounds__(256)
mma_gemm(const __half* __restrict__ A, const __half* __restrict__ Bh,
         const float* __restrict__ bias0, const float* __restrict__ bias1,
         const float* __restrict__ bias2,
         void* C0, void* C1, void* C2) {
    extern __shared__ char sm[];
    uint32_t sbase = smem_u32(sm);

    int tid = threadIdx.x, wid = tid >> 5, lane = tid & 31;
    int bx = blockIdx.x;
    int warpM = (wid >> 2) * 64;           // 0 or 64
    int warpN = (wid & 3) * 64;            // 0,64,128,192

    const __half* srcA = A  + (size_t)blockIdx.y * 128 * KDIM;
    const __half* srcB = Bh + (size_t)bx * 256 * KDIM;

    float acc[4][8][4];
#pragma unroll
    for (int i = 0; i < 4; i++)
#pragma unroll
        for (int j = 0; j < 8; j++)
#pragma unroll
            for (int e = 0; e < 4; e++) acc[i][j][e] = 0.f;

    // copy: (128 A rows + 256 B rows) x 8 x 16B segs = 3072; 12/thread
    auto issue = [&](int c) {
        uint32_t stb = sbase + (uint32_t)((c % NSTAGE) * STAGE_B);
        int k0 = c * BK;
#pragma unroll
        for (int j = 0; j < 12; j++) {
            int idx = tid + j * 256;
            const __half* g;
            uint32_t d;
            if (idx < 1024) {              // A
                int r = idx >> 3, s = idx & 7;
                g = srcA + (size_t)r * KDIM + k0 + s * 8;
                d = stb + (uint32_t)(r * (PSTR * 2) + s * 16);
            } else {                        // B
                int r = (idx - 1024) >> 3, s = idx & 7;
                g = srcB + (size_t)r * KDIM + k0 + s * 8;
                d = stb + (uint32_t)(ARR_A + r * (PSTR * 2) + s * 16);
            }
            asm volatile("cp.async.cg.shared.global [%0], [%1], 16;"
                         :: "r"(d), "l"(g));
        }
        asm volatile("cp.async.commit_group;");
    };

    uint32_t aoff = (uint32_t)((warpM + (lane & 15)) * (PSTR * 2) + (lane >> 4) * 16);
    uint32_t boff = (uint32_t)(ARR_A +
                    (warpN + ((lane >> 4) << 3) + (lane & 7)) * (PSTR * 2) +
                    ((lane >> 3) & 1) * 16);

    const int nch = KDIM / BK;
    issue(0);
    issue(1);
    for (int c = 0; c < nch; c++) {
        if (c + 2 < nch) {
            issue(c + 2);
            asm volatile("cp.async.wait_group 2;");
        } else if (c + 1 < nch) {
            asm volatile("cp.async.wait_group 1;");
        } else {
            asm volatile("cp.async.wait_group 0;");
        }
        __syncthreads();

        uint32_t stage = sbase + (uint32_t)((c % NSTAGE) * STAGE_B);
#pragma unroll
        for (int kk = 0; kk < 4; kk++) {
            uint32_t ah[4][4];
#pragma unroll
            for (int mt = 0; mt < 4; mt++) {
                uint32_t ad = stage + aoff + mt * (16 * PSTR * 2) + kk * 32;
                LDSM_X4(ah[mt][0], ah[mt][1], ah[mt][2], ah[mt][3], ad);
            }
            uint32_t bh[8][2];
#pragma unroll
            for (int np = 0; np < 4; np++) {
                uint32_t bd = stage + boff + np * (16 * PSTR * 2) + kk * 32;
                LDSM_X4(bh[2*np][0], bh[2*np][1], bh[2*np+1][0], bh[2*np+1][1], bd);
            }
#pragma unroll
            for (int mt = 0; mt < 4; mt++)
#pragma unroll
                for (int nt = 0; nt < 8; nt++)
                    MMA16816(acc[mt][nt], ah[mt], bh[nt]);
        }
        __syncthreads();
    }

    // Epilogue: bias + (relu) -> fp32 or fp16 store. Output stride is 512.
    int reg = bx >> 1;
    const float* bias = (reg == 0) ? bias0 : (reg == 1) ? bias1 : bias2;
    void* Cp          = (reg == 0) ? C0    : (reg == 1) ? C1    : C2;
    int row0 = blockIdx.y * 128 + warpM + (lane >> 2);
    int col0 = (bx & 1) * 256 + warpN + (lane & 3) * 2;
#pragma unroll
    for (int mt = 0; mt < 4; mt++) {
#pragma unroll
        for (int nt = 0; nt < 8; nt++) {
            int r = row0 + mt * 16;
            int cc = col0 + nt * 8;
            float b0 = bias[cc], b1 = bias[cc + 1];
            float2 d0, d1;
            d0.x = acc[mt][nt][0] + b0; d0.y = acc[mt][nt][1] + b1;
            d1.x = acc[mt][nt][2] + b0; d1.y = acc[mt][nt][3] + b1;
            if (ACT) {
                d0.x = fmaxf(d0.x, 0.f); d0.y = fmaxf(d0.y, 0.f);
                d1.x = fmaxf(d1.x, 0.f); d1.y = fmaxf(d1.y, 0.f);
            }
            if (HOUT) {
                __half* Ch = (__half*)Cp;
                *(__half2*)(Ch + (size_t)r * 512 + cc)       = __floats2half2_rn(d0.x, d0.y);
                *(__half2*)(Ch + (size_t)(r + 8) * 512 + cc) = __floats2half2_rn(d1.x, d1.y);
            } else {
                float* Cf = (float*)Cp;
                *(float2*)(Cf + (size_t)r * 512 + cc)       = d0;
                *(float2*)(Cf + (size_t)(r + 8) * 512 + cc) = d1;
            }
        }
    }
}

// ---------------------------------------------------------------------------
// Fused causal attention, online softmax, packed f32x2 math.
// One block per (b, n, head): 128 threads, one query row each.
// ---------------------------------------------------------------------------
__global__ void __launch_bounds__(128)
attn_kernel(const int* __restrict__ kpm,
            const __half* __restrict__ Q, const __half* __restrict__ Kp,
            const __half* __restrict__ V, __half* __restrict__ outp) {
    __shared__ float ks[64][64];
    __shared__ float vs[64][64];

    int bid = blockIdx.x;
    int h = bid & 7;
    int n = (bid >> 3) % N_;
    int b = bid / (H_ * N_);
    int tq = threadIdx.x;
    int L  = kpm[b];

    size_t base = ((size_t)(b * T_) * N_ + n) * D_ + h * DH;
    const size_t rstride = (size_t)N_ * D_;

    ull qr2[32], acc2[32];
    {
        const __half* qp = Q + base + (size_t)tq * rstride;
#pragma unroll
        for (int d = 0; d < DH; d += 8) {
            uint4 u = *(const uint4*)(qp + d);
            const __half2* h2 = (const __half2*)&u;
#pragma unroll
            for (int j = 0; j < 4; j++) {
                float2 f = __half22float2(h2[j]);
                qr2[(d >> 1) + j] = (ull)__float_as_uint(f.x)
                                  | ((ull)__float_as_uint(f.y) << 32);
            }
        }
    }
#pragma unroll
    for (int j = 0; j < 32; j++) acc2[j] = 0ull;

    float m = -CUDART_INF_F, l = 0.f;
    int pmax = min(tq, L - 1);

    for (int c0 = 0; c0 < T_; c0 += 64) {
        __syncthreads();
#pragma unroll
        for (int it = 0; it < 4; it++) {
            int e = (threadIdx.x + it * 128) * 8;
            int r = e >> 6, d = e & 63;
            size_t off = base + (size_t)(c0 + r) * rstride + d;
            uint4 ku = *(const uint4*)(Kp + off);
            uint4 vu = *(const uint4*)(V + off);
            const __half2* kh = (const __half2*)&ku;
            const __half2* vh = (const __half2*)&vu;
#pragma unroll
            for (int j = 0; j < 4; j++) {
                *(float2*)&ks[r][d + 2 * j] = __half22float2(kh[j]);
                *(float2*)&vs[r][d + 2 * j] = __half22float2(vh[j]);
            }
        }
        __syncthreads();

        int pend = min(pmax, c0 + 63);
        for (int p = c0; p <= pend; p++) {
            const ull* kr2 = (const ull*)ks[p - c0];
            ull s0 = 0, s1 = 0, s2 = 0, s3 = 0;
#pragma unroll
            for (int j = 0; j < 32; j += 4) {
                FMA2(s0, qr2[j],     kr2[j],     s0);
                FMA2(s1, qr2[j + 1], kr2[j + 1], s1);
                FMA2(s2, qr2[j + 2], kr2[j + 2], s2);
                FMA2(s3, qr2[j + 3], kr2[j + 3], s3);
            }
            ADD2(s0, s0, s1);
            ADD2(s2, s2, s3);
            ADD2(s0, s0, s2);
            float s = (__uint_as_float((uint32_t)s0) +
                       __uint_as_float((uint32_t)(s0 >> 32))) * 0.125f;

            float mn   = fmaxf(m, s);
            float corr = __expf(m - mn);
            float e1   = __expf(s - mn);
            l = l * corr + e1;
            ull corr2 = bcast2(corr), e12 = bcast2(e1);
            const ull* vr2 = (const ull*)vs[p - c0];
#pragma unroll
            for (int j = 0; j < 32; j++) {
                ull t;
                MUL2(t, acc2[j], corr2);
                FMA2(acc2[j], e12, vr2[j], t);
            }
            m = mn;
        }
    }

    float inv = 1.f / l;
    __half* op = outp + base + (size_t)tq * rstride;
#pragma unroll
    for (int j = 0; j < 32; j++) {
        float x = __uint_as_float((uint32_t)acc2[j]) * inv;
        float y = __uint_as_float((uint32_t)(acc2[j] >> 32)) * inv;
        *(__half2*)(op + 2 * j) = __floats2half2_rn(x, y);
    }
}

// ---------------------------------------------------------------------------
extern "C" void kernel_launch(void* const* d_in, const int* in_sizes, int n_in,
                              void* d_out, int out_size) {
    const float* X   = (const float*)d_in[0];
    const float* TLE = (const float*)d_in[1];
    const int*   kpm = (const int*)  d_in[2];
    const float* Wq  = (const float*)d_in[3];
    const float* bq  = (const float*)d_in[4];
    const float* Wk  = (const float*)d_in[5];
    const float* bk  = (const float*)d_in[6];
    const float* Wv  = (const float*)d_in[7];
    const float* bv  = (const float*)d_in[8];
    const float* W1  = (const float*)d_in[9];
    const float* b1  = (const float*)d_in[10];
    const float* W2  = (const float*)d_in[11];
    const float* b2  = (const float*)d_in[12];
    float* out = (float*)d_out;

    __half *pAct, *pWh, *pq, *pk, *pv;
    cudaGetSymbolAddress((void**)&pAct, g_Act);
    cudaGetSymbolAddress((void**)&pWh, g_Wh);
    cudaGetSymbolAddress((void**)&pq, g_q);
    cudaGetSymbolAddress((void**)&pk, g_k);
    cudaGetSymbolAddress((void**)&pv, g_v);

    __half* actR0 = pAct;                       // attn out / W1 input
    __half* actR1 = pAct + (size_t)TOK * D_;    // FFN mid

    cudaFuncSetAttribute((const void*)mma_gemm<1,1,1536>,
                         cudaFuncAttributeMaxDynamicSharedMemorySize, SMEM_B);
    cudaFuncSetAttribute((const void*)mma_gemm<1,1,512>,
                         cudaFuncAttributeMaxDynamicSharedMemorySize, SMEM_B);
    cudaFuncSetAttribute((const void*)mma_gemm<0,0,512>,
                         cudaFuncAttributeMaxDynamicSharedMemorySize, SMEM_B);

    // 1. H = [X, TLE] -> fp16
    conv_H_kernel<<<(size_t)TOK * K3 / 8 / 256, 256>>>(X, TLE);

    // 2. transpose weights -> fp16
    wtrans_kernel<<<3072, 256>>>(Wq, pWh,                     K3);
    wtrans_kernel<<<3072, 256>>>(Wk, pWh + (size_t)512 * K3,  K3);
    wtrans_kernel<<<3072, 256>>>(Wv, pWh + (size_t)1024 * K3, K3);
    wtrans_kernel<<<1024, 256>>>(W1, pWh + WOFF1, D_);
    wtrans_kernel<<<1024, 256>>>(W2, pWh + WOFF2, D_);

    // 3. fused QKV projection (single launch, 6 x 256-wide column blocks)
    mma_gemm<1,1,1536><<<dim3(6, TOK / 128), 256, SMEM_B>>>(
        pAct, pWh, bq, bk, bv, pq, pk, pv);

    // 4. fused causal attention -> fp16 region0
    attn_kernel<<<B_ * N_ * H_, 128>>>(kpm, pq, pk, pv, actR0);

    // 5. FFN
    mma_gemm<1,1,512><<<dim3(2, TOK / 128), 256, SMEM_B>>>(
        actR0, pWh + WOFF1, b1, b1, b1, actR1, actR1, actR1);
    mma_gemm<0,0,512><<<dim3(2, TOK / 128), 256, SMEM_B>>>(
        actR1, pWh + WOFF2, b2, b2, b2, out, out, out);
}

// round 7
// speedup vs baseline: 5.8054x; 1.0214x over previous
#include <cuda_runtime.h>
#include <cuda_fp16.h>
#include <math_constants.h>
#include <cstdint>

// Problem constants
#define B_   16
#define T_   128
#define N_   50
#define D_   512
#define H_   8
#define DH   64
#define TOK  (B_ * T_ * N_)      // 102400 tokens
#define K3   (3 * D_)            // 1536

typedef unsigned long long ull;

// ---------------------------------------------------------------------------
// Scratch (device globals: allocation-free per harness rules)
// ---------------------------------------------------------------------------
__device__ __half g_Act[(size_t)TOK * K3];
__device__ __half g_q[(size_t)TOK * D_];
__device__ __half g_k[(size_t)TOK * D_];
__device__ __half g_v[(size_t)TOK * D_];
// Transposed fp16 weights: [Wq;Wk;Wv] stacked (1536 rows x K=1536), then W1, W2.
#define WOFF1 2359296
#define WOFF2 2621440
__device__ __half g_Wh[2883584];

// ---------------------------------------------------------------------------
// helpers
// ---------------------------------------------------------------------------
__device__ __forceinline__ uint32_t smem_u32(const void* p) {
    uint32_t a;
    asm("{ .reg .u64 t; cvta.to.shared.u64 t, %1; cvt.u32.u64 %0, t; }"
        : "=r"(a) : "l"(p));
    return a;
}

#define LDSM_X4(r0, r1, r2, r3, addr)                                         \
    asm volatile("ldmatrix.sync.aligned.m8n8.x4.shared.b16 {%0,%1,%2,%3}, [%4];" \
                 : "=r"(r0), "=r"(r1), "=r"(r2), "=r"(r3) : "r"(addr))

#define MMA16816(d, a, b)                                                     \
    asm volatile("mma.sync.aligned.m16n8k16.row.col.f32.f16.f16.f32 "         \
                 "{%0,%1,%2,%3}, {%4,%5,%6,%7}, {%8,%9}, {%0,%1,%2,%3};"      \
                 : "+f"((d)[0]), "+f"((d)[1]), "+f"((d)[2]), "+f"((d)[3])     \
                 : "r"((a)[0]), "r"((a)[1]), "r"((a)[2]), "r"((a)[3]),        \
                   "r"((b)[0]), "r"((b)[1]))

// packed f32x2 (sm_100+ base ISA)
#define FMA2(d, a, b, c) \
    asm("fma.rn.f32x2 %0, %1, %2, %3;" : "=l"(d) : "l"(a), "l"(b), "l"(c))
#define MUL2(d, a, b) \
    asm("mul.rn.f32x2 %0, %1, %2;" : "=l"(d) : "l"(a), "l"(b))
#define ADD2(d, a, b) \
    asm("add.rn.f32x2 %0, %1, %2;" : "=l"(d) : "l"(a), "l"(b))

__device__ __forceinline__ ull bcast2(float f) {
    uint32_t u = __float_as_uint(f);
    return (ull)u | ((ull)u << 32);
}

// ---------------------------------------------------------------------------
// All weight transposes in one launch:
//   Wq/Wk/Wv [1536,512] fp32 -> stacked Wt rows [1536 x K3] fp16
//   W1/W2    [512,512]  fp32 -> Wt [512 x 512] fp16 at WOFF1/WOFF2
// ---------------------------------------------------------------------------
__global__ void wtrans_all_kernel(const float* __restrict__ Wq,
                                  const float* __restrict__ Wk,
                                  const float* __restrict__ Wv,
                                  const float* __restrict__ W1,
                                  const float* __restrict__ W2) {
    int idx = blockIdx.x * 256 + threadIdx.x;
    const float* src;
    float v;
    if (idx < WOFF1) {
        int sel = idx / 786432, i = idx - sel * 786432;
        int n = i / K3, k = i - n * K3;
        src = (sel == 0) ? Wq : (sel == 1) ? Wk : Wv;
        v = src[(size_t)k * 512 + n];
    } else {
        int j = idx - WOFF1;
        int sel = j >> 18, i = j & 262143;          // 262144 = 512*512
        int n = i >> 9, k = i & 511;
        src = sel ? W2 : W1;
        v = src[(size_t)k * 512 + n];
    }
    g_Wh[idx] = __float2half_rn(v);
}

// ---------------------------------------------------------------------------
// H = concat(X, TLE) -> fp16, 8 elems/thread
// ---------------------------------------------------------------------------
__global__ void conv_H_kernel(const float* __restrict__ X,
                              const float* __restrict__ TLE) {
    size_t i = ((size_t)blockIdx.x * 256 + threadIdx.x) * 8;
    size_t tok = i / K3;
    int c = (int)(i % K3);
    const float* src = (c < D_) ? (X + tok * D_ + c)
                                : (TLE + tok * (size_t)(2 * D_) + (c - D_));
    float4 a = *(const float4*)src;
    float4 b = *(const float4*)(src + 4);
    float f[8] = {a.x, a.y, a.z, a.w, b.x, b.y, b.z, b.w};
    __half h[8];
#pragma unroll
    for (int j = 0; j < 8; j++) h[j] = __float2half_rn(f[j]);
    *(uint4*)(g_Act + i) = *(uint4*)h;
}

// ---------------------------------------------------------------------------
// Tensor-core GEMM (HMMA fp16): C[*,512] = act(A @ Wt^T + bias)
//   CTA tile 128x256, 8 warps (2x4), warp tile 64x64, BK=64, 3-stage cp.async,
//   register double-buffered fragments, one barrier per K-chunk.
// ---------------------------------------------------------------------------
#define BK       64
#define PSTR     72                        // halves per padded row (144 B)
#define ARR_A    (128 * PSTR * 2)          // 18432
#define ARR_Bt   (256 * PSTR * 2)          // 36864
#define STAGE_B  (ARR_A + ARR_Bt)          // 55296
#define NSTAGE   3
#define SMEM_B   (NSTAGE * STAGE_B)        // 165888

template<int ACT, int HOUT, int KDIM>
__global__ void __launch_bounds__(256)
mma_gemm(const __half* __restrict__ A, const __half* __restrict__ Bh,
         const float* __restrict__ bias0, const float* __restrict__ bias1,
         const float* __restrict__ bias2,
         void* C0, void* C1, void* C2) {
    extern __shared__ char sm[];
    uint32_t sbase = smem_u32(sm);

    int tid = threadIdx.x, wid = tid >> 5, lane = tid & 31;
    int bx = blockIdx.x;
    int warpM = (wid >> 2) * 64;           // 0 or 64
    int warpN = (wid & 3) * 64;            // 0,64,128,192

    const __half* srcA = A  + (size_t)blockIdx.y * 128 * KDIM;
    const __half* srcB = Bh + (size_t)bx * 256 * KDIM;

    float acc[4][8][4];
#pragma unroll
    for (int i = 0; i < 4; i++)
#pragma unroll
        for (int j = 0; j < 8; j++)
#pragma unroll
            for (int e = 0; e < 4; e++) acc[i][j][e] = 0.f;

    // copy: (128 A rows + 256 B rows) x 8 x 16B segs = 3072; 12/thread
    auto issue = [&](int c) {
        uint32_t stb = sbase + (uint32_t)((c % NSTAGE) * STAGE_B);
        int k0 = c * BK;
#pragma unroll
        for (int j = 0; j < 12; j++) {
            int idx = tid + j * 256;
            const __half* g;
            uint32_t d;
            if (idx < 1024) {              // A
                int r = idx >> 3, s = idx & 7;
                g = srcA + (size_t)r * KDIM + k0 + s * 8;
                d = stb + (uint32_t)(r * (PSTR * 2) + s * 16);
            } else {                        // B
                int r = (idx - 1024) >> 3, s = idx & 7;
                g = srcB + (size_t)r * KDIM + k0 + s * 8;
                d = stb + (uint32_t)(ARR_A + r * (PSTR * 2) + s * 16);
            }
            asm volatile("cp.async.cg.shared.global [%0], [%1], 16;"
                         :: "r"(d), "l"(g));
        }
        asm volatile("cp.async.commit_group;");
    };

    uint32_t aoff = (uint32_t)((warpM + (lane & 15)) * (PSTR * 2) + (lane >> 4) * 16);
    uint32_t boff = (uint32_t)(ARR_A +
                    (warpN + ((lane >> 4) << 3) + (lane & 7)) * (PSTR * 2) +
                    ((lane >> 3) & 1) * 16);

    // fragment loader (one kk-step worth of A and B tiles)
    auto ldfrag = [&](uint32_t stage, int kk, uint32_t (*Af)[4], uint32_t (*Bf)[2]) {
#pragma unroll
        for (int mt = 0; mt < 4; mt++) {
            uint32_t ad = stage + aoff + mt * (16 * PSTR * 2) + kk * 32;
            LDSM_X4(Af[mt][0], Af[mt][1], Af[mt][2], Af[mt][3], ad);
        }
#pragma unroll
        for (int np = 0; np < 4; np++) {
            uint32_t bd = stage + boff + np * (16 * PSTR * 2) + kk * 32;
            LDSM_X4(Bf[2*np][0], Bf[2*np][1], Bf[2*np+1][0], Bf[2*np+1][1], bd);
        }
    };

    uint32_t ah[2][4][4], bh[2][8][2];

    const int nch = KDIM / BK;
    issue(0);
    issue(1);
    for (int c = 0; c < nch; c++) {
        if (c + 1 < nch) asm volatile("cp.async.wait_group 1;");
        else             asm volatile("cp.async.wait_group 0;");
        __syncthreads();
        if (c + 2 < nch) issue(c + 2);

        uint32_t stage = sbase + (uint32_t)((c % NSTAGE) * STAGE_B);
        ldfrag(stage, 0, ah[0], bh[0]);
#pragma unroll
        for (int kk = 0; kk < 4; kk++) {
            int cur = kk & 1;
            if (kk < 3) ldfrag(stage, kk + 1, ah[cur ^ 1], bh[cur ^ 1]);
#pragma unroll
            for (int mt = 0; mt < 4; mt++)
#pragma unroll
                for (int nt = 0; nt < 8; nt++)
                    MMA16816(acc[mt][nt], ah[cur][mt], bh[cur][nt]);
        }
    }

    // Epilogue: bias + (relu) -> fp32 or fp16 store. Output stride is 512.
    int reg = bx >> 1;
    const float* bias = (reg == 0) ? bias0 : (reg == 1) ? bias1 : bias2;
    void* Cp          = (reg == 0) ? C0    : (reg == 1) ? C1    : C2;
    int row0 = blockIdx.y * 128 + warpM + (lane >> 2);
    int col0 = (bx & 1) * 256 + warpN + (lane & 3) * 2;
#pragma unroll
    for (int mt = 0; mt < 4; mt++) {
#pragma unroll
        for (int nt = 0; nt < 8; nt++) {
            int r = row0 + mt * 16;
            int cc = col0 + nt * 8;
            float b0 = bias[cc], b1 = bias[cc + 1];
            float2 d0, d1;
            d0.x = acc[mt][nt][0] + b0; d0.y = acc[mt][nt][1] + b1;
            d1.x = acc[mt][nt][2] + b0; d1.y = acc[mt][nt][3] + b1;
            if (ACT) {
                d0.x = fmaxf(d0.x, 0.f); d0.y = fmaxf(d0.y, 0.f);
                d1.x = fmaxf(d1.x, 0.f); d1.y = fmaxf(d1.y, 0.f);
            }
            if (HOUT) {
                __half* Ch = (__half*)Cp;
                *(__half2*)(Ch + (size_t)r * 512 + cc)       = __floats2half2_rn(d0.x, d0.y);
                *(__half2*)(Ch + (size_t)(r + 8) * 512 + cc) = __floats2half2_rn(d1.x, d1.y);
            } else {
                float* Cf = (float*)Cp;
                *(float2*)(Cf + (size_t)r * 512 + cc)       = d0;
                *(float2*)(Cf + (size_t)(r + 8) * 512 + cc) = d1;
            }
        }
    }
}

// ---------------------------------------------------------------------------
// Fused causal attention, online softmax, packed f32x2 math.
// ---------------------------------------------------------------------------
__global__ void __launch_bounds__(128)
attn_kernel(const int* __restrict__ kpm,
            const __half* __restrict__ Q, const __half* __restrict__ Kp,
            const __half* __restrict__ V, __half* __restrict__ outp) {
    __shared__ float ks[64][64];
    __shared__ float vs[64][64];

    int bid = blockIdx.x;
    int h = bid & 7;
    int n = (bid >> 3) % N_;
    int b = bid / (H_ * N_);
    int tq = threadIdx.x;
    int L  = kpm[b];

    size_t base = ((size_t)(b * T_) * N_ + n) * D_ + h * DH;
    const size_t rstride = (size_t)N_ * D_;

    ull qr2[32], acc2[32];
    {
        const __half* qp = Q + base + (size_t)tq * rstride;
#pragma unroll
        for (int d = 0; d < DH; d += 8) {
            uint4 u = *(const uint4*)(qp + d);
            const __half2* h2 = (const __half2*)&u;
#pragma unroll
            for (int j = 0; j < 4; j++) {
                float2 f = __half22float2(h2[j]);
                qr2[(d >> 1) + j] = (ull)__float_as_uint(f.x)
                                  | ((ull)__float_as_uint(f.y) << 32);
            }
        }
    }
#pragma unroll
    for (int j = 0; j < 32; j++) acc2[j] = 0ull;

    float m = -CUDART_INF_F, l = 0.f;
    int pmax = min(tq, L - 1);

    for (int c0 = 0; c0 < T_; c0 += 64) {
        __syncthreads();
#pragma unroll
        for (int it = 0; it < 4; it++) {
            int e = (threadIdx.x + it * 128) * 8;
            int r = e >> 6, d = e & 63;
            size_t off = base + (size_t)(c0 + r) * rstride + d;
            uint4 ku = *(const uint4*)(Kp + off);
            uint4 vu = *(const uint4*)(V + off);
            const __half2* kh = (const __half2*)&ku;
            const __half2* vh = (const __half2*)&vu;
#pragma unroll
            for (int j = 0; j < 4; j++) {
                *(float2*)&ks[r][d + 2 * j] = __half22float2(kh[j]);
                *(float2*)&vs[r][d + 2 * j] = __half22float2(vh[j]);
            }
        }
        __syncthreads();

        int pend = min(pmax, c0 + 63);
        for (int p = c0; p <= pend; p++) {
            const ull* kr2 = (const ull*)ks[p - c0];
            ull s0 = 0, s1 = 0, s2 = 0, s3 = 0;
#pragma unroll
            for (int j = 0; j < 32; j += 4) {
                FMA2(s0, qr2[j],     kr2[j],     s0);
                FMA2(s1, qr2[j + 1], kr2[j + 1], s1);
                FMA2(s2, qr2[j + 2], kr2[j + 2], s2);
                FMA2(s3, qr2[j + 3], kr2[j + 3], s3);
            }
            ADD2(s0, s0, s1);
            ADD2(s2, s2, s3);
            ADD2(s0, s0, s2);
            float s = (__uint_as_float((uint32_t)s0) +
                       __uint_as_float((uint32_t)(s0 >> 32))) * 0.125f;

            float mn   = fmaxf(m, s);
            float corr = __expf(m - mn);
            float e1   = __expf(s - mn);
            l = l * corr + e1;
            ull corr2 = bcast2(corr), e12 = bcast2(e1);
            const ull* vr2 = (const ull*)vs[p - c0];
#pragma unroll
            for (int j = 0; j < 32; j++) {
                ull t;
                MUL2(t, acc2[j], corr2);
                FMA2(acc2[j], e12, vr2[j], t);
            }
            m = mn;
        }
    }

    float inv = 1.f / l;
    __half* op = outp + base + (size_t)tq * rstride;
#pragma unroll
    for (int j = 0; j < 32; j++) {
        float x = __uint_as_float((uint32_t)acc2[j]) * inv;
        float y = __uint_as_float((uint32_t)(acc2[j] >> 32)) * inv;
        *(__half2*)(op + 2 * j) = __floats2half2_rn(x, y);
    }
}

// ---------------------------------------------------------------------------
extern "C" void kernel_launch(void* const* d_in, const int* in_sizes, int n_in,
                              void* d_out, int out_size) {
    const float* X   = (const float*)d_in[0];
    const float* TLE = (const float*)d_in[1];
    const int*   kpm = (const int*)  d_in[2];
    const float* Wq  = (const float*)d_in[3];
    const float* bq  = (const float*)d_in[4];
    const float* Wk  = (const float*)d_in[5];
    const float* bk  = (const float*)d_in[6];
    const float* Wv  = (const float*)d_in[7];
    const float* bv  = (const float*)d_in[8];
    const float* W1  = (const float*)d_in[9];
    const float* b1  = (const float*)d_in[10];
    const float* W2  = (const float*)d_in[11];
    const float* b2  = (const float*)d_in[12];
    float* out = (float*)d_out;

    __half *pAct, *pWh, *pq, *pk, *pv;
    cudaGetSymbolAddress((void**)&pAct, g_Act);
    cudaGetSymbolAddress((void**)&pWh, g_Wh);
    cudaGetSymbolAddress((void**)&pq, g_q);
    cudaGetSymbolAddress((void**)&pk, g_k);
    cudaGetSymbolAddress((void**)&pv, g_v);

    __half* actR0 = pAct;                       // attn out / W1 input
    __half* actR1 = pAct + (size_t)TOK * D_;    // FFN mid

    cudaFuncSetAttribute((const void*)mma_gemm<1,1,1536>,
                         cudaFuncAttributeMaxDynamicSharedMemorySize, SMEM_B);
    cudaFuncSetAttribute((const void*)mma_gemm<1,1,512>,
                         cudaFuncAttributeMaxDynamicSharedMemorySize, SMEM_B);
    cudaFuncSetAttribute((const void*)mma_gemm<0,0,512>,
                         cudaFuncAttributeMaxDynamicSharedMemorySize, SMEM_B);

    // 1. transpose all weights -> fp16 (single launch)
    wtrans_all_kernel<<<2883584 / 256, 256>>>(Wq, Wk, Wv, W1, W2);

    // 2. H = [X, TLE] -> fp16
    conv_H_kernel<<<(size_t)TOK * K3 / 8 / 256, 256>>>(X, TLE);

    // 3. fused QKV projection (single launch, 6 x 256-wide column blocks)
    mma_gemm<1,1,1536><<<dim3(6, TOK / 128), 256, SMEM_B>>>(
        pAct, pWh, bq, bk, bv, pq, pk, pv);

    // 4. fused causal attention -> fp16 region0
    attn_kernel<<<B_ * N_ * H_, 128>>>(kpm, pq, pk, pv, actR0);

    // 5. FFN
    mma_gemm<1,1,512><<<dim3(2, TOK / 128), 256, SMEM_B>>>(
        actR0, pWh + WOFF1, b1, b1, b1, actR1, actR1, actR1);
    mma_gemm<0,0,512><<<dim3(2, TOK / 128), 256, SMEM_B>>>(
        actR1, pWh + WOFF2, b2, b2, b2, out, out, out);
}

// round 8
// speedup vs baseline: 6.6756x; 1.1499x over previous
#include <cuda_runtime.h>
#include <cuda_fp16.h>
#include <math_constants.h>
#include <cstdint>

// Problem constants
#define B_   16
#define T_   128
#define N_   50
#define D_   512
#define H_   8
#define DH   64
#define TOK  (B_ * T_ * N_)      // 102400 tokens
#define K3   (3 * D_)            // 1536

typedef unsigned long long ull;

// ---------------------------------------------------------------------------
// Scratch (device globals: allocation-free per harness rules)
// ---------------------------------------------------------------------------
__device__ __half g_Act[(size_t)TOK * K3];
__device__ __half g_q[(size_t)TOK * D_];
__device__ __half g_k[(size_t)TOK * D_];
__device__ __half g_v[(size_t)TOK * D_];
// Transposed fp16 weights: [Wq;Wk;Wv] stacked (1536 rows x K=1536), then W1, W2.
#define WOFF1 2359296
#define WOFF2 2621440
__device__ __half g_Wh[2883584];

// ---------------------------------------------------------------------------
// helpers
// ---------------------------------------------------------------------------
__device__ __forceinline__ uint32_t smem_u32(const void* p) {
    uint32_t a;
    asm("{ .reg .u64 t; cvta.to.shared.u64 t, %1; cvt.u32.u64 %0, t; }"
        : "=r"(a) : "l"(p));
    return a;
}

#define LDSM_X4(r0, r1, r2, r3, addr)                                         \
    asm volatile("ldmatrix.sync.aligned.m8n8.x4.shared.b16 {%0,%1,%2,%3}, [%4];" \
                 : "=r"(r0), "=r"(r1), "=r"(r2), "=r"(r3) : "r"(addr))

#define LDSM_X4_T(r0, r1, r2, r3, addr)                                       \
    asm volatile("ldmatrix.sync.aligned.m8n8.x4.trans.shared.b16 {%0,%1,%2,%3}, [%4];" \
                 : "=r"(r0), "=r"(r1), "=r"(r2), "=r"(r3) : "r"(addr))

#define MMA16816(d, a, b)                                                     \
    asm volatile("mma.sync.aligned.m16n8k16.row.col.f32.f16.f16.f32 "         \
                 "{%0,%1,%2,%3}, {%4,%5,%6,%7}, {%8,%9}, {%0,%1,%2,%3};"      \
                 : "+f"((d)[0]), "+f"((d)[1]), "+f"((d)[2]), "+f"((d)[3])     \
                 : "r"((a)[0]), "r"((a)[1]), "r"((a)[2]), "r"((a)[3]),        \
                   "r"((b)[0]), "r"((b)[1]))

__device__ __forceinline__ uint32_t packh2(float x, float y) {
    __half2 h = __floats2half2_rn(x, y);
    return *(uint32_t*)&h;
}

// ---------------------------------------------------------------------------
// All weight transposes in one launch.
// ---------------------------------------------------------------------------
__global__ void wtrans_all_kernel(const float* __restrict__ Wq,
                                  const float* __restrict__ Wk,
                                  const float* __restrict__ Wv,
                                  const float* __restrict__ W1,
                                  const float* __restrict__ W2) {
    int idx = blockIdx.x * 256 + threadIdx.x;
    const float* src;
    float v;
    if (idx < WOFF1) {
        int sel = idx / 786432, i = idx - sel * 786432;
        int n = i / K3, k = i - n * K3;
        src = (sel == 0) ? Wq : (sel == 1) ? Wk : Wv;
        v = src[(size_t)k * 512 + n];
    } else {
        int j = idx - WOFF1;
        int sel = j >> 18, i = j & 262143;
        int n = i >> 9, k = i & 511;
        src = sel ? W2 : W1;
        v = src[(size_t)k * 512 + n];
    }
    g_Wh[idx] = __float2half_rn(v);
}

// ---------------------------------------------------------------------------
// H = concat(X, TLE) -> fp16, 8 elems/thread
// ---------------------------------------------------------------------------
__global__ void conv_H_kernel(const float* __restrict__ X,
                              const float* __restrict__ TLE) {
    size_t i = ((size_t)blockIdx.x * 256 + threadIdx.x) * 8;
    size_t tok = i / K3;
    int c = (int)(i % K3);
    const float* src = (c < D_) ? (X + tok * D_ + c)
                                : (TLE + tok * (size_t)(2 * D_) + (c - D_));
    float4 a = *(const float4*)src;
    float4 b = *(const float4*)(src + 4);
    float f[8] = {a.x, a.y, a.z, a.w, b.x, b.y, b.z, b.w};
    __half h[8];
#pragma unroll
    for (int j = 0; j < 8; j++) h[j] = __float2half_rn(f[j]);
    *(uint4*)(g_Act + i) = *(uint4*)h;
}

// ---------------------------------------------------------------------------
// Tensor-core GEMM (unchanged from R7)
// ---------------------------------------------------------------------------
#define BK       64
#define PSTR     72
#define ARR_A    (128 * PSTR * 2)
#define ARR_Bt   (256 * PSTR * 2)
#define STAGE_B  (ARR_A + ARR_Bt)
#define NSTAGE   3
#define SMEM_B   (NSTAGE * STAGE_B)

template<int ACT, int HOUT, int KDIM>
__global__ void __launch_bounds__(256)
mma_gemm(const __half* __restrict__ A, const __half* __restrict__ Bh,
         const float* __restrict__ bias0, const float* __restrict__ bias1,
         const float* __restrict__ bias2,
         void* C0, void* C1, void* C2) {
    extern __shared__ char sm[];
    uint32_t sbase = smem_u32(sm);

    int tid = threadIdx.x, wid = tid >> 5, lane = tid & 31;
    int bx = blockIdx.x;
    int warpM = (wid >> 2) * 64;
    int warpN = (wid & 3) * 64;

    const __half* srcA = A  + (size_t)blockIdx.y * 128 * KDIM;
    const __half* srcB = Bh + (size_t)bx * 256 * KDIM;

    float acc[4][8][4];
#pragma unroll
    for (int i = 0; i < 4; i++)
#pragma unroll
        for (int j = 0; j < 8; j++)
#pragma unroll
            for (int e = 0; e < 4; e++) acc[i][j][e] = 0.f;

    auto issue = [&](int c) {
        uint32_t stb = sbase + (uint32_t)((c % NSTAGE) * STAGE_B);
        int k0 = c * BK;
#pragma unroll
        for (int j = 0; j < 12; j++) {
            int idx = tid + j * 256;
            const __half* g;
            uint32_t d;
            if (idx < 1024) {
                int r = idx >> 3, s = idx & 7;
                g = srcA + (size_t)r * KDIM + k0 + s * 8;
                d = stb + (uint32_t)(r * (PSTR * 2) + s * 16);
            } else {
                int r = (idx - 1024) >> 3, s = idx & 7;
                g = srcB + (size_t)r * KDIM + k0 + s * 8;
                d = stb + (uint32_t)(ARR_A + r * (PSTR * 2) + s * 16);
            }
            asm volatile("cp.async.cg.shared.global [%0], [%1], 16;"
                         :: "r"(d), "l"(g));
        }
        asm volatile("cp.async.commit_group;");
    };

    uint32_t aoff = (uint32_t)((warpM + (lane & 15)) * (PSTR * 2) + (lane >> 4) * 16);
    uint32_t boff = (uint32_t)(ARR_A +
                    (warpN + ((lane >> 4) << 3) + (lane & 7)) * (PSTR * 2) +
                    ((lane >> 3) & 1) * 16);

    auto ldfrag = [&](uint32_t stage, int kk, uint32_t (*Af)[4], uint32_t (*Bf)[2]) {
#pragma unroll
        for (int mt = 0; mt < 4; mt++) {
            uint32_t ad = stage + aoff + mt * (16 * PSTR * 2) + kk * 32;
            LDSM_X4(Af[mt][0], Af[mt][1], Af[mt][2], Af[mt][3], ad);
        }
#pragma unroll
        for (int np = 0; np < 4; np++) {
            uint32_t bd = stage + boff + np * (16 * PSTR * 2) + kk * 32;
            LDSM_X4(Bf[2*np][0], Bf[2*np][1], Bf[2*np+1][0], Bf[2*np+1][1], bd);
        }
    };

    uint32_t ah[2][4][4], bh[2][8][2];

    const int nch = KDIM / BK;
    issue(0);
    issue(1);
    for (int c = 0; c < nch; c++) {
        if (c + 1 < nch) asm volatile("cp.async.wait_group 1;");
        else             asm volatile("cp.async.wait_group 0;");
        __syncthreads();
        if (c + 2 < nch) issue(c + 2);

        uint32_t stage = sbase + (uint32_t)((c % NSTAGE) * STAGE_B);
        ldfrag(stage, 0, ah[0], bh[0]);
#pragma unroll
        for (int kk = 0; kk < 4; kk++) {
            int cur = kk & 1;
            if (kk < 3) ldfrag(stage, kk + 1, ah[cur ^ 1], bh[cur ^ 1]);
#pragma unroll
            for (int mt = 0; mt < 4; mt++)
#pragma unroll
                for (int nt = 0; nt < 8; nt++)
                    MMA16816(acc[mt][nt], ah[cur][mt], bh[cur][nt]);
        }
    }

    int reg = bx >> 1;
    const float* bias = (reg == 0) ? bias0 : (reg == 1) ? bias1 : bias2;
    void* Cp          = (reg == 0) ? C0    : (reg == 1) ? C1    : C2;
    int row0 = blockIdx.y * 128 + warpM + (lane >> 2);
    int col0 = (bx & 1) * 256 + warpN + (lane & 3) * 2;
#pragma unroll
    for (int mt = 0; mt < 4; mt++) {
#pragma unroll
        for (int nt = 0; nt < 8; nt++) {
            int r = row0 + mt * 16;
            int cc = col0 + nt * 8;
            float b0 = bias[cc], b1 = bias[cc + 1];
            float2 d0, d1;
            d0.x = acc[mt][nt][0] + b0; d0.y = acc[mt][nt][1] + b1;
            d1.x = acc[mt][nt][2] + b0; d1.y = acc[mt][nt][3] + b1;
            if (ACT) {
                d0.x = fmaxf(d0.x, 0.f); d0.y = fmaxf(d0.y, 0.f);
                d1.x = fmaxf(d1.x, 0.f); d1.y = fmaxf(d1.y, 0.f);
            }
            if (HOUT) {
                __half* Ch = (__half*)Cp;
                *(__half2*)(Ch + (size_t)r * 512 + cc)       = __floats2half2_rn(d0.x, d0.y);
                *(__half2*)(Ch + (size_t)(r + 8) * 512 + cc) = __floats2half2_rn(d1.x, d1.y);
            } else {
                float* Cf = (float*)Cp;
                *(float2*)(Cf + (size_t)r * 512 + cc)       = d0;
                *(float2*)(Cf + (size_t)(r + 8) * 512 + cc) = d1;
            }
        }
    }
}

// ---------------------------------------------------------------------------
// Tensor-core causal attention. One CTA per (b, n, head), 8 warps.
// Warp w owns q-rows [w*16, w*16+16). Full 128-wide score rows (T fits),
// softmax in fragments, P fp16 reuses the C->A fragment layout identity.
// ---------------------------------------------------------------------------
#define ATT_ROWB 144                       // 72 halves per padded row
#define ATT_ARR  (128 * ATT_ROWB)          // 18432
#define ATT_SMEM (3 * ATT_ARR)             // 55296

__global__ void __launch_bounds__(256)
attn_tc_kernel(const int* __restrict__ kpm,
               const __half* __restrict__ Q, const __half* __restrict__ Kp,
               const __half* __restrict__ V, __half* __restrict__ outp) {
    extern __shared__ char sm[];
    uint32_t sb = smem_u32(sm);

    int bid = blockIdx.x;
    int h = bid & 7;
    int n = (bid >> 3) % N_;
    int b = bid / (H_ * N_);
    int tid = threadIdx.x, wq = tid >> 5, lane = tid & 31;
    int L = kpm[b];

    size_t base = ((size_t)(b * T_) * N_ + n) * D_ + h * DH;
    const size_t rstride = (size_t)N_ * D_;

    // stage Q, K, V tiles (128 x 64 fp16 each, padded rows)
#pragma unroll
    for (int j = 0; j < 12; j++) {
        int idx = tid + j * 256;
        int arr = idx >> 10, rem = idx & 1023;
        int r = rem >> 3, s = rem & 7;
        const __half* src = ((arr == 0) ? Q : (arr == 1) ? Kp : V)
                            + base + (size_t)r * rstride + s * 8;
        *(uint4*)(sm + arr * ATT_ARR + r * ATT_ROWB + s * 16) = *(const uint4*)src;
    }
    __syncthreads();

    // Q fragments for this warp's 16 rows: 4 k-tiles
    uint32_t qa[4][4];
#pragma unroll
    for (int kt = 0; kt < 4; kt++) {
        uint32_t ad = sb + (wq * 16 + (lane & 15)) * ATT_ROWB
                         + (kt * 16 + (lane >> 4) * 8) * 2;
        LDSM_X4(qa[kt][0], qa[kt][1], qa[kt][2], qa[kt][3], ad);
    }

    // S = Q K^T : 16 n-tiles (8 keys each)
    float sa[16][4];
#pragma unroll
    for (int nt = 0; nt < 16; nt++)
#pragma unroll
        for (int e = 0; e < 4; e++) sa[nt][e] = 0.f;

#pragma unroll
    for (int nt2 = 0; nt2 < 8; nt2++) {
#pragma unroll
        for (int kt = 0; kt < 4; kt++) {
            uint32_t bk0[2], bk1[2];
            uint32_t bd = sb + ATT_ARR
                        + (nt2 * 16 + ((lane >> 4) << 3) + (lane & 7)) * ATT_ROWB
                        + (kt * 16 + ((lane >> 3) & 1) * 8) * 2;
            LDSM_X4(bk0[0], bk0[1], bk1[0], bk1[1], bd);
            MMA16816(sa[2 * nt2],     qa[kt], bk0);
            MMA16816(sa[2 * nt2 + 1], qa[kt], bk1);
        }
    }

    // mask + softmax (rows r0 and r0+8)
    const float NEGINF = -CUDART_INF_F;
    int r0 = wq * 16 + (lane >> 2);
    int r1 = r0 + 8;
    int c2 = (lane & 3) * 2;
    float m0 = NEGINF, m1 = NEGINF;
#pragma unroll
    for (int nt = 0; nt < 16; nt++) {
        int c0 = nt * 8 + c2;
#pragma unroll
        for (int e = 0; e < 4; e++) {
            int col = c0 + (e & 1);
            int row = (e < 2) ? r0 : r1;
            float s = sa[nt][e] * 0.125f;
            if (col > row || col >= L) s = NEGINF;
            sa[nt][e] = s;
            if (e < 2) m0 = fmaxf(m0, s); else m1 = fmaxf(m1, s);
        }
    }
    m0 = fmaxf(m0, __shfl_xor_sync(0xffffffffu, m0, 1));
    m0 = fmaxf(m0, __shfl_xor_sync(0xffffffffu, m0, 2));
    m1 = fmaxf(m1, __shfl_xor_sync(0xffffffffu, m1, 1));
    m1 = fmaxf(m1, __shfl_xor_sync(0xffffffffu, m1, 2));

    float l0 = 0.f, l1 = 0.f;
#pragma unroll
    for (int nt = 0; nt < 16; nt++) {
#pragma unroll
        for (int e = 0; e < 4; e++) {
            float p = __expf(sa[nt][e] - ((e < 2) ? m0 : m1));
            sa[nt][e] = p;
            if (e < 2) l0 += p; else l1 += p;
        }
    }
    l0 += __shfl_xor_sync(0xffffffffu, l0, 1);
    l0 += __shfl_xor_sync(0xffffffffu, l0, 2);
    l1 += __shfl_xor_sync(0xffffffffu, l1, 1);
    l1 += __shfl_xor_sync(0xffffffffu, l1, 2);

    // O = P V : contraction over 8 key-tiles; 8 dim-tiles of 8
    float oa[8][4];
#pragma unroll
    for (int dt = 0; dt < 8; dt++)
#pragma unroll
        for (int e = 0; e < 4; e++) oa[dt][e] = 0.f;

#pragma unroll
    for (int kt = 0; kt < 8; kt++) {
        uint32_t pa[4];
        pa[0] = packh2(sa[2 * kt][0],     sa[2 * kt][1]);
        pa[1] = packh2(sa[2 * kt][2],     sa[2 * kt][3]);
        pa[2] = packh2(sa[2 * kt + 1][0], sa[2 * kt + 1][1]);
        pa[3] = packh2(sa[2 * kt + 1][2], sa[2 * kt + 1][3]);
#pragma unroll
        for (int dt2 = 0; dt2 < 4; dt2++) {
            uint32_t bv0[2], bv1[2];
            uint32_t bd = sb + 2 * ATT_ARR
                        + (kt * 16 + ((lane >> 3) & 1) * 8 + (lane & 7)) * ATT_ROWB
                        + (dt2 * 16 + ((lane >> 4) << 3)) * 2;
            LDSM_X4_T(bv0[0], bv0[1], bv1[0], bv1[1], bd);
            MMA16816(oa[2 * dt2],     pa, bv0);
            MMA16816(oa[2 * dt2 + 1], pa, bv1);
        }
    }

    float inv0 = 1.f / l0, inv1 = 1.f / l1;
    __half* op0 = outp + base + (size_t)r0 * rstride;
    __half* op1 = outp + base + (size_t)r1 * rstride;
#pragma unroll
    for (int dt = 0; dt < 8; dt++) {
        int c = dt * 8 + c2;
        *(__half2*)(op0 + c) = __floats2half2_rn(oa[dt][0] * inv0, oa[dt][1] * inv0);
        *(__half2*)(op1 + c) = __floats2half2_rn(oa[dt][2] * inv1, oa[dt][3] * inv1);
    }
}

// ---------------------------------------------------------------------------
extern "C" void kernel_launch(void* const* d_in, const int* in_sizes, int n_in,
                              void* d_out, int out_size) {
    const float* X   = (const float*)d_in[0];
    const float* TLE = (const float*)d_in[1];
    const int*   kpm = (const int*)  d_in[2];
    const float* Wq  = (const float*)d_in[3];
    const float* bq  = (const float*)d_in[4];
    const float* Wk  = (const float*)d_in[5];
    const float* bk  = (const float*)d_in[6];
    const float* Wv  = (const float*)d_in[7];
    const float* bv  = (const float*)d_in[8];
    const float* W1  = (const float*)d_in[9];
    const float* b1  = (const float*)d_in[10];
    const float* W2  = (const float*)d_in[11];
    const float* b2  = (const float*)d_in[12];
    float* out = (float*)d_out;

    __half *pAct, *pWh, *pq, *pk, *pv;
    cudaGetSymbolAddress((void**)&pAct, g_Act);
    cudaGetSymbolAddress((void**)&pWh, g_Wh);
    cudaGetSymbolAddress((void**)&pq, g_q);
    cudaGetSymbolAddress((void**)&pk, g_k);
    cudaGetSymbolAddress((void**)&pv, g_v);

    __half* actR0 = pAct;                       // attn out / W1 input
    __half* actR1 = pAct + (size_t)TOK * D_;    // FFN mid

    cudaFuncSetAttribute((const void*)mma_gemm<1,1,1536>,
                         cudaFuncAttributeMaxDynamicSharedMemorySize, SMEM_B);
    cudaFuncSetAttribute((const void*)mma_gemm<1,1,512>,
                         cudaFuncAttributeMaxDynamicSharedMemorySize, SMEM_B);
    cudaFuncSetAttribute((const void*)mma_gemm<0,0,512>,
                         cudaFuncAttributeMaxDynamicSharedMemorySize, SMEM_B);
    cudaFuncSetAttribute((const void*)attn_tc_kernel,
                         cudaFuncAttributeMaxDynamicSharedMemorySize, ATT_SMEM);

    // 1. transpose all weights -> fp16 (single launch)
    wtrans_all_kernel<<<2883584 / 256, 256>>>(Wq, Wk, Wv, W1, W2);

    // 2. H = [X, TLE] -> fp16
    conv_H_kernel<<<(size_t)TOK * K3 / 8 / 256, 256>>>(X, TLE);

    // 3. fused QKV projection
    mma_gemm<1,1,1536><<<dim3(6, TOK / 128), 256, SMEM_B>>>(
        pAct, pWh, bq, bk, bv, pq, pk, pv);

    // 4. tensor-core causal attention -> fp16 region0
    attn_tc_kernel<<<B_ * N_ * H_, 256, ATT_SMEM>>>(kpm, pq, pk, pv, actR0);

    // 5. FFN
    mma_gemm<1,1,512><<<dim3(2, TOK / 128), 256, SMEM_B>>>(
        actR0, pWh + WOFF1, b1, b1, b1, actR1, actR1, actR1);
    mma_gemm<0,0,512><<<dim3(2, TOK / 128), 256, SMEM_B>>>(
        actR1, pWh + WOFF2, b2, b2, b2, out, out, out);
}